// round 1
// baseline (speedup 1.0000x reference)
#include <cuda_runtime.h>
#include <math.h>

// AxialSelfAttention2d: B=2,S=64,L=256,H=8,C=64,D=512
// Pipeline:
//   qkv1 = x @ w_row^T + b_row            (SGEMM 32768x1536x512)
//   rowattn per (b,s,h) over L=256        (flash-style, smem K/V)
//   out1 = LN(x + rowattn)
//   qkv2 = out1 @ w_col^T + b_col
//   colattn per (b,l,h) over S=64
//   out  = LN(out1 + colattn)

#define M_TOK 32768
#define N3D 1536
#define KD 512

__device__ float g_qkv[(size_t)M_TOK * N3D];   // 201 MB scratch
__device__ float g_attn[(size_t)M_TOK * 512];  // 67 MB
__device__ float g_out1[(size_t)M_TOK * 512];  // 67 MB

// ---------------------------------------------------------------------------
// SGEMM: C[M,N] = A[M,K] @ W[N,K]^T + bias[N]   (fp32, 128x128x16 tiles)
// ---------------------------------------------------------------------------
#define BM 128
#define BN 128
#define BK 16

__global__ __launch_bounds__(256, 2)
void sgemm_bias(const float* __restrict__ A, const float* __restrict__ W,
                const float* __restrict__ bias, float* __restrict__ C) {
    __shared__ float As[BK][BM + 4];
    __shared__ float Ws[BK][BN + 4];
    const int tid = threadIdx.x;
    const int m0 = blockIdx.y * BM;
    const int n0 = blockIdx.x * BN;
    const int tx = tid & 15;
    const int ty = tid >> 4;
    const int lm = tid >> 1;          // 0..127
    const int lk = (tid & 1) * 8;     // 0 or 8

    float acc[8][8] = {};
    const float* Ap = A + (m0 + lm) * KD + lk;
    const float* Wp = W + (n0 + lm) * KD + lk;

    float4 a0 = *(const float4*)(Ap);
    float4 a1 = *(const float4*)(Ap + 4);
    float4 w0 = *(const float4*)(Wp);
    float4 w1 = *(const float4*)(Wp + 4);

    for (int k0 = 0; k0 < KD; k0 += BK) {
        __syncthreads();
        As[lk+0][lm]=a0.x; As[lk+1][lm]=a0.y; As[lk+2][lm]=a0.z; As[lk+3][lm]=a0.w;
        As[lk+4][lm]=a1.x; As[lk+5][lm]=a1.y; As[lk+6][lm]=a1.z; As[lk+7][lm]=a1.w;
        Ws[lk+0][lm]=w0.x; Ws[lk+1][lm]=w0.y; Ws[lk+2][lm]=w0.z; Ws[lk+3][lm]=w0.w;
        Ws[lk+4][lm]=w1.x; Ws[lk+5][lm]=w1.y; Ws[lk+6][lm]=w1.z; Ws[lk+7][lm]=w1.w;
        __syncthreads();
        if (k0 + BK < KD) {             // prefetch next tile under compute
            Ap += BK; Wp += BK;
            a0 = *(const float4*)(Ap);
            a1 = *(const float4*)(Ap + 4);
            w0 = *(const float4*)(Wp);
            w1 = *(const float4*)(Wp + 4);
        }
        #pragma unroll
        for (int k = 0; k < BK; k++) {
            float af[8], bf[8];
            *(float4*)(af)     = *(const float4*)&As[k][ty*4];
            *(float4*)(af + 4) = *(const float4*)&As[k][64 + ty*4];
            *(float4*)(bf)     = *(const float4*)&Ws[k][tx*4];
            *(float4*)(bf + 4) = *(const float4*)&Ws[k][64 + tx*4];
            #pragma unroll
            for (int i = 0; i < 8; i++)
                #pragma unroll
                for (int j = 0; j < 8; j++)
                    acc[i][j] += af[i] * bf[j];
        }
    }
    #pragma unroll
    for (int i = 0; i < 8; i++) {
        int m = m0 + ((i < 4) ? (ty*4 + i) : (64 + ty*4 + i - 4));
        #pragma unroll
        for (int jv = 0; jv < 2; jv++) {
            int n = n0 + jv*64 + tx*4;
            float4 bv = *(const float4*)&bias[n];
            float4 o;
            o.x = acc[i][jv*4+0] + bv.x;
            o.y = acc[i][jv*4+1] + bv.y;
            o.z = acc[i][jv*4+2] + bv.z;
            o.w = acc[i][jv*4+3] + bv.w;
            *(float4*)&C[m * N3D + n] = o;
        }
    }
}

// ---------------------------------------------------------------------------
// Attention over NT tokens for one (b, fixedaxis, h). K/V resident in smem.
// One warp per query row; each lane owns KPL=NT/32 keys for scores and
// 2 channels for the PV accumulation.
// NT=256: row attention (over L). NT=64: column attention (over S).
// ---------------------------------------------------------------------------
template<int NT, int KPL>
__global__ void attn_kernel(const float* __restrict__ qkv, float* __restrict__ out) {
    extern __shared__ float smem[];
    float* kt = smem;              // K transposed in float4 groups: [(c/4)*NT + j]*4 + c%4
    float* vs = kt + NT * 64;      // V natural [j][64]
    float* qs = vs + NT * 64;      // per-warp q row [8][64]
    float* ps = qs + 8 * 64;       // per-warp probs [8][NT]

    const int tid = threadIdx.x;
    const int bid = blockIdx.x;
    const int h = bid & 7;
    int qbase, qstride, obase, ostride;
    if (NT == 256) {               // row attention: fixed (b,s), tokens = l
        int s = (bid >> 3) & 63;
        int b = bid >> 9;
        int tok0 = (b * 64 + s) * 256;
        qbase = tok0 * 1536 + h * 64;  qstride = 1536;
        obase = tok0 * 512 + h * 64;   ostride = 512;
    } else {                       // column attention: fixed (b,l), tokens = s
        int l = (bid >> 3) & 255;
        int b = bid >> 11;
        int tok0 = b * 16384 + l;
        qbase = tok0 * 1536 + h * 64;  qstride = 256 * 1536;
        obase = tok0 * 512 + h * 64;   ostride = 256 * 512;
    }

    for (int idx = tid; idx < NT * 64; idx += 256) {
        int j = idx >> 6, c = idx & 63;
        int g = qbase + j * qstride + c;
        float kv = qkv[g + 512];
        float vv = qkv[g + 1024];
        int cg = c >> 2, ci = c & 3;
        kt[((cg * NT + j) << 2) + ci] = kv;
        vs[idx] = vv;
    }
    __syncthreads();

    const int warp = tid >> 5, lane = tid & 31;
    float* qsw = qs + warp * 64;
    float* psw = ps + warp * NT;

    for (int r = warp; r < NT; r += 8) {
        *(float2*)&qsw[2 * lane] = *(const float2*)&qkv[qbase + r * qstride + 2 * lane];
        __syncwarp();
        float s[KPL];
        #pragma unroll
        for (int kk = 0; kk < KPL; kk++) s[kk] = 0.f;
        #pragma unroll
        for (int cg = 0; cg < 16; cg++) {
            float4 qv = *(const float4*)&qsw[cg * 4];
            #pragma unroll
            for (int kk = 0; kk < KPL; kk++) {
                float4 kv = *(const float4*)&kt[(cg * NT + lane + kk * 32) << 2];
                s[kk] += qv.x * kv.x + qv.y * kv.y + qv.z * kv.z + qv.w * kv.w;
            }
        }
        // softmax over all NT keys (no 1/sqrt(C) scaling, matching reference)
        float mx = s[0];
        #pragma unroll
        for (int kk = 1; kk < KPL; kk++) mx = fmaxf(mx, s[kk]);
        #pragma unroll
        for (int o = 16; o > 0; o >>= 1) mx = fmaxf(mx, __shfl_xor_sync(0xffffffffu, mx, o));
        float sum = 0.f;
        #pragma unroll
        for (int kk = 0; kk < KPL; kk++) { s[kk] = __expf(s[kk] - mx); sum += s[kk]; }
        #pragma unroll
        for (int o = 16; o > 0; o >>= 1) sum += __shfl_xor_sync(0xffffffffu, sum, o);
        #pragma unroll
        for (int kk = 0; kk < KPL; kk++) psw[lane + kk * 32] = s[kk];
        __syncwarp();
        // PV: lane owns channels 2*lane, 2*lane+1
        float ax = 0.f, ay = 0.f;
        #pragma unroll 4
        for (int j4 = 0; j4 < NT / 4; j4++) {
            float4 p4 = *(const float4*)&psw[j4 * 4];
            const float* vrow = vs + j4 * 4 * 64 + 2 * lane;
            float2 v0 = *(const float2*)(vrow);
            float2 v1 = *(const float2*)(vrow + 64);
            float2 v2 = *(const float2*)(vrow + 128);
            float2 v3 = *(const float2*)(vrow + 192);
            ax += p4.x * v0.x + p4.y * v1.x + p4.z * v2.x + p4.w * v3.x;
            ay += p4.x * v0.y + p4.y * v1.y + p4.z * v2.y + p4.w * v3.y;
        }
        float inv = 1.f / sum;
        float2 o2; o2.x = ax * inv; o2.y = ay * inv;
        *(float2*)&out[obase + r * ostride + 2 * lane] = o2;
        __syncwarp();
    }
}

// ---------------------------------------------------------------------------
// out = LayerNorm(a + b) * g + beta, D=512, one warp per row
// ---------------------------------------------------------------------------
__global__ void add_ln(const float* __restrict__ a, const float* __restrict__ b,
                       const float* __restrict__ g, const float* __restrict__ be,
                       float* __restrict__ out) {
    int row = blockIdx.x * 8 + (threadIdx.x >> 5);
    int lane = threadIdx.x & 31;
    const float* pa = a + row * 512;
    const float* pb = b + row * 512;
    float v[16];
    float sum = 0.f;
    #pragma unroll
    for (int i = 0; i < 4; i++) {
        int c = lane * 4 + i * 128;
        float4 x = *(const float4*)&pa[c];
        float4 y = *(const float4*)&pb[c];
        v[i*4+0] = x.x + y.x; v[i*4+1] = x.y + y.y;
        v[i*4+2] = x.z + y.z; v[i*4+3] = x.w + y.w;
        sum += v[i*4+0] + v[i*4+1] + v[i*4+2] + v[i*4+3];
    }
    #pragma unroll
    for (int o = 16; o > 0; o >>= 1) sum += __shfl_xor_sync(0xffffffffu, sum, o);
    float mu = sum * (1.f / 512.f);
    float var = 0.f;
    #pragma unroll
    for (int i = 0; i < 16; i++) { float d = v[i] - mu; var += d * d; }
    #pragma unroll
    for (int o = 16; o > 0; o >>= 1) var += __shfl_xor_sync(0xffffffffu, var, o);
    float rstd = rsqrtf(var * (1.f / 512.f) + 1e-5f);
    float* po = out + row * 512;
    #pragma unroll
    for (int i = 0; i < 4; i++) {
        int c = lane * 4 + i * 128;
        float4 gg = *(const float4*)&g[c];
        float4 bb = *(const float4*)&be[c];
        float4 o4;
        o4.x = (v[i*4+0] - mu) * rstd * gg.x + bb.x;
        o4.y = (v[i*4+1] - mu) * rstd * gg.y + bb.y;
        o4.z = (v[i*4+2] - mu) * rstd * gg.z + bb.z;
        o4.w = (v[i*4+3] - mu) * rstd * gg.w + bb.w;
        *(float4*)&po[c] = o4;
    }
}

// ---------------------------------------------------------------------------

extern "C" void kernel_launch(void* const* d_in, const int* in_sizes, int n_in,
                              void* d_out, int out_size) {
    const float* x     = (const float*)d_in[0];
    const float* w_row = (const float*)d_in[1];
    const float* b_row = (const float*)d_in[2];
    const float* w_col = (const float*)d_in[3];
    const float* b_col = (const float*)d_in[4];
    const float* g1    = (const float*)d_in[5];
    const float* be1   = (const float*)d_in[6];
    const float* g2    = (const float*)d_in[7];
    const float* be2   = (const float*)d_in[8];
    float* out = (float*)d_out;

    float *qkv, *attn, *out1;
    cudaGetSymbolAddress((void**)&qkv,  g_qkv);
    cudaGetSymbolAddress((void**)&attn, g_attn);
    cudaGetSymbolAddress((void**)&out1, g_out1);

    const int smem_row = (256 * 64 * 2 + 8 * 64 + 8 * 256) * 4;  // 141312 B
    const int smem_col = (64 * 64 * 2 + 8 * 64 + 8 * 64) * 4;    // 36864 B
    cudaFuncSetAttribute(attn_kernel<256, 8>,
                         cudaFuncAttributeMaxDynamicSharedMemorySize, smem_row);

    dim3 ggrid(N3D / BN, M_TOK / BM);   // (12, 256)

    sgemm_bias<<<ggrid, 256>>>(x, w_row, b_row, qkv);
    attn_kernel<256, 8><<<1024, 256, smem_row>>>(qkv, attn);
    add_ln<<<M_TOK / 8, 256>>>(x, attn, g1, be1, out1);
    sgemm_bias<<<ggrid, 256>>>(out1, w_col, b_col, qkv);
    attn_kernel<64, 2><<<4096, 256, smem_col>>>(qkv, attn);
    add_ln<<<M_TOK / 8, 256>>>(out1, attn, g2, be2, out);
}

// round 3
// speedup vs baseline: 1.3365x; 1.3365x over previous
#include <cuda_runtime.h>
#include <math.h>
#include <cstdint>

// AxialSelfAttention2d: B=2,S=64,L=256,H=8,C=64,D=512
// All-fp32, f32x2 packed FMA (base sm_103 feature; tcgen05 unavailable:
// harness compiles to .target sm_103 without the 'a' suffix).

#define M_TOK 32768
#define N3D 1536
#define KD 512

__device__ float g_qkv[(size_t)M_TOK * N3D];
__device__ float g_attn[(size_t)M_TOK * 512];
__device__ float g_out1[(size_t)M_TOK * 512];

// ---------------------------------------------------------------------------
// f32x2 packed helpers
// ---------------------------------------------------------------------------
__device__ __forceinline__ uint64_t pack2(float x, float y) {
    uint64_t r;
    asm("mov.b64 %0, {%1,%2};" : "=l"(r) : "f"(x), "f"(y));
    return r;
}
__device__ __forceinline__ void fma2(uint64_t& d, uint64_t a, uint64_t b) {
    asm("fma.rn.f32x2 %0, %1, %2, %0;" : "+l"(d) : "l"(a), "l"(b));
}
__device__ __forceinline__ float2 unpack2(uint64_t v) {
    float2 r;
    asm("mov.b64 {%0,%1}, %2;" : "=f"(r.x), "=f"(r.y) : "l"(v));
    return r;
}

// ---------------------------------------------------------------------------
// SGEMM: C[M,N] = A[M,K] @ W[N,K]^T + bias[N], 128x128x16 tiles, f32x2 inner.
// ---------------------------------------------------------------------------
#define BM 128
#define BN 128
#define BK 16

__global__ __launch_bounds__(256, 2)
void sgemm_bias(const float* __restrict__ A, const float* __restrict__ W,
                const float* __restrict__ bias, float* __restrict__ C) {
    __shared__ float As[BK][BM + 4];
    __shared__ float Ws[BK][BN + 4];
    const int tid = threadIdx.x;
    const int m0 = blockIdx.y * BM;
    const int n0 = blockIdx.x * BN;
    const int tx = tid & 15;
    const int ty = tid >> 4;
    const int lm = tid >> 1;
    const int lk = (tid & 1) * 8;

    uint64_t acc2[8][4];
    #pragma unroll
    for (int i = 0; i < 8; i++)
        #pragma unroll
        for (int j = 0; j < 4; j++) acc2[i][j] = 0ull;

    const float* Ap = A + (size_t)(m0 + lm) * KD + lk;
    const float* Wp = W + (size_t)(n0 + lm) * KD + lk;

    float4 a0 = *(const float4*)(Ap);
    float4 a1 = *(const float4*)(Ap + 4);
    float4 w0 = *(const float4*)(Wp);
    float4 w1 = *(const float4*)(Wp + 4);

    for (int k0 = 0; k0 < KD; k0 += BK) {
        __syncthreads();
        As[lk+0][lm]=a0.x; As[lk+1][lm]=a0.y; As[lk+2][lm]=a0.z; As[lk+3][lm]=a0.w;
        As[lk+4][lm]=a1.x; As[lk+5][lm]=a1.y; As[lk+6][lm]=a1.z; As[lk+7][lm]=a1.w;
        Ws[lk+0][lm]=w0.x; Ws[lk+1][lm]=w0.y; Ws[lk+2][lm]=w0.z; Ws[lk+3][lm]=w0.w;
        Ws[lk+4][lm]=w1.x; Ws[lk+5][lm]=w1.y; Ws[lk+6][lm]=w1.z; Ws[lk+7][lm]=w1.w;
        __syncthreads();
        if (k0 + BK < KD) {
            Ap += BK; Wp += BK;
            a0 = *(const float4*)(Ap);
            a1 = *(const float4*)(Ap + 4);
            w0 = *(const float4*)(Wp);
            w1 = *(const float4*)(Wp + 4);
        }
        #pragma unroll
        for (int k = 0; k < BK; k++) {
            float af[8];
            float bf[8] __attribute__((aligned(16)));
            *(float4*)(af)     = *(const float4*)&As[k][ty*4];
            *(float4*)(af + 4) = *(const float4*)&As[k][64 + ty*4];
            *(float4*)(bf)     = *(const float4*)&Ws[k][tx*4];
            *(float4*)(bf + 4) = *(const float4*)&Ws[k][64 + tx*4];
            uint64_t b2[4];
            b2[0] = ((const uint64_t*)bf)[0];
            b2[1] = ((const uint64_t*)bf)[1];
            b2[2] = ((const uint64_t*)bf)[2];
            b2[3] = ((const uint64_t*)bf)[3];
            #pragma unroll
            for (int i = 0; i < 8; i++) {
                uint64_t a2 = pack2(af[i], af[i]);
                #pragma unroll
                for (int j = 0; j < 4; j++) fma2(acc2[i][j], a2, b2[j]);
            }
        }
    }
    #pragma unroll
    for (int i = 0; i < 8; i++) {
        int m = m0 + ((i < 4) ? (ty*4 + i) : (64 + ty*4 + i - 4));
        #pragma unroll
        for (int jv = 0; jv < 2; jv++) {
            int n = n0 + jv*64 + tx*4;
            float4 bv = *(const float4*)&bias[n];
            float2 p0 = unpack2(acc2[i][jv*2 + 0]);
            float2 p1 = unpack2(acc2[i][jv*2 + 1]);
            float4 o;
            o.x = p0.x + bv.x; o.y = p0.y + bv.y;
            o.z = p1.x + bv.z; o.w = p1.y + bv.w;
            *(float4*)&C[(size_t)m * N3D + n] = o;
        }
    }
}

// ---------------------------------------------------------------------------
// Attention over NT tokens for one (b, fixedaxis, h). K/V resident in smem.
// R=4 query rows per warp pass: K/V smem traffic amortized 4x.
// f32x2 packed score + PV accumulation.
// ---------------------------------------------------------------------------
template<int NT, int KPL>
__global__ void attn_kernel(const float* __restrict__ qkv, float* __restrict__ out) {
    extern __shared__ float fsmem[];
    float* kt = fsmem;                 // K as float4 groups: [(c/4)*NT + j]*4 + c%4
    float* vs = kt + NT * 64;          // V natural [j][64]
    float* qs = vs + NT * 64;          // per-warp 4 q rows [8][4][64]
    float* ps = qs + 8 * 4 * 64;       // per-warp probs [8][4][NT]

    const int tid = threadIdx.x;
    const int bid = blockIdx.x;
    const int h = bid & 7;
    int qbase, qstride, obase, ostride;
    if (NT == 256) {
        int s = (bid >> 3) & 63;
        int b = bid >> 9;
        int tok0 = (b * 64 + s) * 256;
        qbase = tok0 * 1536 + h * 64;  qstride = 1536;
        obase = tok0 * 512 + h * 64;   ostride = 512;
    } else {
        int l = (bid >> 3) & 255;
        int b = bid >> 11;
        int tok0 = b * 16384 + l;
        qbase = tok0 * 1536 + h * 64;  qstride = 256 * 1536;
        obase = tok0 * 512 + h * 64;   ostride = 256 * 512;
    }

    for (int idx = tid; idx < NT * 64; idx += 256) {
        int j = idx >> 6, c = idx & 63;
        int g = qbase + j * qstride + c;
        float kv = qkv[g + 512];
        float vv = qkv[g + 1024];
        int cg = c >> 2, ci = c & 3;
        kt[((cg * NT + j) << 2) + ci] = kv;
        vs[idx] = vv;
    }
    __syncthreads();

    const int warp = tid >> 5, lane = tid & 31;
    float* qsw = qs + warp * 4 * 64;
    float* psw = ps + warp * 4 * NT;

    for (int r0 = warp * 4; r0 < NT; r0 += 32) {
        #pragma unroll
        for (int rr = 0; rr < 4; rr++)
            *(float2*)&qsw[rr * 64 + 2 * lane] =
                *(const float2*)&qkv[qbase + (r0 + rr) * qstride + 2 * lane];
        __syncwarp();

        uint64_t s2[4][KPL];
        #pragma unroll
        for (int rr = 0; rr < 4; rr++)
            #pragma unroll
            for (int kk = 0; kk < KPL; kk++) s2[rr][kk] = 0ull;

        #pragma unroll
        for (int cg = 0; cg < 16; cg++) {
            uint64_t q2[4][2];
            #pragma unroll
            for (int rr = 0; rr < 4; rr++) {
                ulonglong2 t = *(const ulonglong2*)&qsw[rr * 64 + cg * 4];
                q2[rr][0] = t.x; q2[rr][1] = t.y;
            }
            #pragma unroll
            for (int kk = 0; kk < KPL; kk++) {
                ulonglong2 kv = *(const ulonglong2*)&kt[(cg * NT + lane + kk * 32) << 2];
                #pragma unroll
                for (int rr = 0; rr < 4; rr++) {
                    fma2(s2[rr][kk], q2[rr][0], kv.x);
                    fma2(s2[rr][kk], q2[rr][1], kv.y);
                }
            }
        }

        float inv[4];
        #pragma unroll
        for (int rr = 0; rr < 4; rr++) {
            float s[KPL];
            #pragma unroll
            for (int kk = 0; kk < KPL; kk++) {
                float2 p = unpack2(s2[rr][kk]);
                s[kk] = p.x + p.y;
            }
            float mx = s[0];
            #pragma unroll
            for (int kk = 1; kk < KPL; kk++) mx = fmaxf(mx, s[kk]);
            #pragma unroll
            for (int o = 16; o > 0; o >>= 1) mx = fmaxf(mx, __shfl_xor_sync(0xffffffffu, mx, o));
            float sum = 0.f;
            #pragma unroll
            for (int kk = 0; kk < KPL; kk++) { s[kk] = __expf(s[kk] - mx); sum += s[kk]; }
            #pragma unroll
            for (int o = 16; o > 0; o >>= 1) sum += __shfl_xor_sync(0xffffffffu, sum, o);
            #pragma unroll
            for (int kk = 0; kk < KPL; kk++) psw[rr * NT + lane + kk * 32] = s[kk];
            inv[rr] = 1.f / sum;
        }
        __syncwarp();

        // PV: lane owns channels (2*lane, 2*lane+1); V loads shared across 4 rows.
        uint64_t acc[4] = {0ull, 0ull, 0ull, 0ull};
        #pragma unroll 2
        for (int j4 = 0; j4 < NT / 4; j4++) {
            const float* vrow = vs + j4 * 4 * 64 + 2 * lane;
            uint64_t v0 = *(const uint64_t*)(vrow);
            uint64_t v1 = *(const uint64_t*)(vrow + 64);
            uint64_t v2 = *(const uint64_t*)(vrow + 128);
            uint64_t v3 = *(const uint64_t*)(vrow + 192);
            #pragma unroll
            for (int rr = 0; rr < 4; rr++) {
                float4 p4 = *(const float4*)&psw[rr * NT + j4 * 4];
                fma2(acc[rr], pack2(p4.x, p4.x), v0);
                fma2(acc[rr], pack2(p4.y, p4.y), v1);
                fma2(acc[rr], pack2(p4.z, p4.z), v2);
                fma2(acc[rr], pack2(p4.w, p4.w), v3);
            }
        }
        #pragma unroll
        for (int rr = 0; rr < 4; rr++) {
            float2 o2 = unpack2(acc[rr]);
            o2.x *= inv[rr]; o2.y *= inv[rr];
            *(float2*)&out[obase + (size_t)(r0 + rr) * ostride + 2 * lane] = o2;
        }
        __syncwarp();
    }
}

// ---------------------------------------------------------------------------
// out = LayerNorm(a + b) * g + beta, D=512, one warp per row
// ---------------------------------------------------------------------------
__global__ void add_ln(const float* __restrict__ a, const float* __restrict__ b,
                       const float* __restrict__ g, const float* __restrict__ be,
                       float* __restrict__ out) {
    int row = blockIdx.x * 8 + (threadIdx.x >> 5);
    int lane = threadIdx.x & 31;
    const float* pa = a + (size_t)row * 512;
    const float* pb = b + (size_t)row * 512;
    float v[16];
    float sum = 0.f;
    #pragma unroll
    for (int i = 0; i < 4; i++) {
        int c = lane * 4 + i * 128;
        float4 x = *(const float4*)&pa[c];
        float4 y = *(const float4*)&pb[c];
        v[i*4+0] = x.x + y.x; v[i*4+1] = x.y + y.y;
        v[i*4+2] = x.z + y.z; v[i*4+3] = x.w + y.w;
        sum += v[i*4+0] + v[i*4+1] + v[i*4+2] + v[i*4+3];
    }
    #pragma unroll
    for (int o = 16; o > 0; o >>= 1) sum += __shfl_xor_sync(0xffffffffu, sum, o);
    float mu = sum * (1.f / 512.f);
    float var = 0.f;
    #pragma unroll
    for (int i = 0; i < 16; i++) { float d = v[i] - mu; var += d * d; }
    #pragma unroll
    for (int o = 16; o > 0; o >>= 1) var += __shfl_xor_sync(0xffffffffu, var, o);
    float rstd = rsqrtf(var * (1.f / 512.f) + 1e-5f);
    float* po = out + (size_t)row * 512;
    #pragma unroll
    for (int i = 0; i < 4; i++) {
        int c = lane * 4 + i * 128;
        float4 gg = *(const float4*)&g[c];
        float4 bb = *(const float4*)&be[c];
        float4 o4;
        o4.x = (v[i*4+0] - mu) * rstd * gg.x + bb.x;
        o4.y = (v[i*4+1] - mu) * rstd * gg.y + bb.y;
        o4.z = (v[i*4+2] - mu) * rstd * gg.z + bb.z;
        o4.w = (v[i*4+3] - mu) * rstd * gg.w + bb.w;
        *(float4*)&po[c] = o4;
    }
}

// ---------------------------------------------------------------------------

extern "C" void kernel_launch(void* const* d_in, const int* in_sizes, int n_in,
                              void* d_out, int out_size) {
    const float* x     = (const float*)d_in[0];
    const float* w_row = (const float*)d_in[1];
    const float* b_row = (const float*)d_in[2];
    const float* w_col = (const float*)d_in[3];
    const float* b_col = (const float*)d_in[4];
    const float* g1    = (const float*)d_in[5];
    const float* be1   = (const float*)d_in[6];
    const float* g2    = (const float*)d_in[7];
    const float* be2   = (const float*)d_in[8];
    float* out = (float*)d_out;

    float *qkv, *attn, *out1;
    cudaGetSymbolAddress((void**)&qkv,  g_qkv);
    cudaGetSymbolAddress((void**)&attn, g_attn);
    cudaGetSymbolAddress((void**)&out1, g_out1);

    const int smem_row = (256 * 64 * 2 + 8 * 4 * 64 + 8 * 4 * 256) * 4;  // 172032 B
    const int smem_col = (64 * 64 * 2 + 8 * 4 * 64 + 8 * 4 * 64) * 4;    // 49152 B
    cudaFuncSetAttribute(attn_kernel<256, 8>,
                         cudaFuncAttributeMaxDynamicSharedMemorySize, smem_row);
    cudaFuncSetAttribute(attn_kernel<64, 2>,
                         cudaFuncAttributeMaxDynamicSharedMemorySize, smem_col);

    dim3 ggrid(N3D / BN, M_TOK / BM);   // (12, 256)

    sgemm_bias<<<ggrid, 256>>>(x, w_row, b_row, qkv);
    attn_kernel<256, 8><<<1024, 256, smem_row>>>(qkv, attn);
    add_ln<<<M_TOK / 8, 256>>>(x, attn, g1, be1, out1);
    sgemm_bias<<<ggrid, 256>>>(out1, w_col, b_col, qkv);
    attn_kernel<64, 2><<<4096, 256, smem_col>>>(qkv, attn);
    add_ln<<<M_TOK / 8, 256>>>(out1, attn, g2, be2, out);
}

// round 4
// speedup vs baseline: 1.9338x; 1.4469x over previous
#include <cuda_runtime.h>
#include <cuda_bf16.h>
#include <math.h>
#include <cstdint>

// AxialSelfAttention2d: B=2,S=64,L=256,H=8,C=64,D=512
// Projections via mma.sync bf16 hi/lo split (base-ISA tensor cores; tcgen05
// unavailable: harness targets sm_103 without 'a'). Attention/LN in fp32.

#define M_TOK 32768
#define N3D 1536
#define KD 512

__device__ float g_qkv[(size_t)M_TOK * N3D];
__device__ float g_attn[(size_t)M_TOK * 512];
__device__ float g_out1[(size_t)M_TOK * 512];
__device__ __nv_bfloat16 g_ahi[(size_t)M_TOK * KD];
__device__ __nv_bfloat16 g_alo[(size_t)M_TOK * KD];
__device__ __nv_bfloat16 g_whi[(size_t)N3D * KD];
__device__ __nv_bfloat16 g_wlo[(size_t)N3D * KD];

// ---------------------------------------------------------------------------
// helpers
// ---------------------------------------------------------------------------
__device__ __forceinline__ uint32_t smem_u32(const void* p) {
    uint32_t a;
    asm("{ .reg .u64 t; cvta.to.shared.u64 t, %1; cvt.u32.u64 %0, t; }" : "=r"(a) : "l"(p));
    return a;
}
__device__ __forceinline__ void ldsm4(uint32_t* r, uint32_t a) {
    asm volatile("ldmatrix.sync.aligned.m8n8.x4.shared.b16 {%0,%1,%2,%3}, [%4];"
        : "=r"(r[0]), "=r"(r[1]), "=r"(r[2]), "=r"(r[3]) : "r"(a));
}
__device__ __forceinline__ void ldsm2(uint32_t* r, uint32_t a) {
    asm volatile("ldmatrix.sync.aligned.m8n8.x2.shared.b16 {%0,%1}, [%2];"
        : "=r"(r[0]), "=r"(r[1]) : "r"(a));
}
__device__ __forceinline__ void mma_bf16(float* c, const uint32_t* a, const uint32_t* b) {
    asm volatile("mma.sync.aligned.m16n8k16.row.col.f32.bf16.bf16.f32 "
        "{%0,%1,%2,%3}, {%4,%5,%6,%7}, {%8,%9}, {%0,%1,%2,%3};"
        : "+f"(c[0]), "+f"(c[1]), "+f"(c[2]), "+f"(c[3])
        : "r"(a[0]), "r"(a[1]), "r"(a[2]), "r"(a[3]), "r"(b[0]), "r"(b[1]));
}
__device__ __forceinline__ uint64_t pack2(float x, float y) {
    uint64_t r;
    asm("mov.b64 %0, {%1,%2};" : "=l"(r) : "f"(x), "f"(y));
    return r;
}
__device__ __forceinline__ void fma2(uint64_t& d, uint64_t a, uint64_t b) {
    asm("fma.rn.f32x2 %0, %1, %2, %0;" : "+l"(d) : "l"(a), "l"(b));
}
__device__ __forceinline__ float2 unpack2(uint64_t v) {
    float2 r;
    asm("mov.b64 {%0,%1}, %2;" : "=f"(r.x), "=f"(r.y) : "l"(v));
    return r;
}

// ---------------------------------------------------------------------------
// hi/lo bf16 split: hi = bf16(a), lo = bf16(a - float(hi))
// ---------------------------------------------------------------------------
__global__ void split_bf16(const float* __restrict__ in, __nv_bfloat16* __restrict__ hi,
                           __nv_bfloat16* __restrict__ lo, int n4) {
    int i = blockIdx.x * 256 + threadIdx.x;
    if (i >= n4) return;
    float4 v = ((const float4*)in)[i];
    __nv_bfloat16 hx = __float2bfloat16(v.x), hy = __float2bfloat16(v.y);
    __nv_bfloat16 hz = __float2bfloat16(v.z), hw = __float2bfloat16(v.w);
    __nv_bfloat16 lx = __float2bfloat16(v.x - __bfloat162float(hx));
    __nv_bfloat16 ly = __float2bfloat16(v.y - __bfloat162float(hy));
    __nv_bfloat16 lz = __float2bfloat16(v.z - __bfloat162float(hz));
    __nv_bfloat16 lw = __float2bfloat16(v.w - __bfloat162float(hw));
    ((__nv_bfloat162*)hi)[2*i]   = __nv_bfloat162(hx, hy);
    ((__nv_bfloat162*)hi)[2*i+1] = __nv_bfloat162(hz, hw);
    ((__nv_bfloat162*)lo)[2*i]   = __nv_bfloat162(lx, ly);
    ((__nv_bfloat162*)lo)[2*i+1] = __nv_bfloat162(lz, lw);
}

// ---------------------------------------------------------------------------
// GEMM via mma.sync: C[M,1536] = (Ahi+Alo)(Whi+Wlo)^T + bias (3 products)
// CTA 128x128, 8 warps (2m x 4n), warp tile 64x32, K staged 32 per iter.
// Smem rows padded to 80B -> conflict-free ldmatrix.
// ---------------------------------------------------------------------------
#define RS 80  // smem row stride bytes (64 data + 16 pad)

__global__ __launch_bounds__(256, 1)
void gemm_mma(const __nv_bfloat16* __restrict__ ahi, const __nv_bfloat16* __restrict__ alo,
              const __nv_bfloat16* __restrict__ whi, const __nv_bfloat16* __restrict__ wlo,
              const float* __restrict__ bias, float* __restrict__ C) {
    __shared__ char smem[4 * 128 * RS];   // 40960 B: [Ahi|Alo|Whi|Wlo], 128 rows each
    const uint32_t sb = smem_u32(smem);
    const int tid = threadIdx.x;
    const int lane = tid & 31, warp = tid >> 5;
    const int wm = (warp >> 2) * 64;
    const int wn = (warp & 3) * 32;
    const int m0 = blockIdx.y * 128;
    const int n0 = blockIdx.x * 128;

    // cooperative load: 2048 16B-vectors per stage, 8 per thread
    const __nv_bfloat16* gsrc[8];
    uint32_t sdst[8];
    #pragma unroll
    for (int i = 0; i < 8; i++) {
        int f = tid + i * 256;
        int region = f >> 9;             // 0:Ahi 1:Alo 2:Whi 3:Wlo
        int r = (f & 511) >> 2, v = f & 3;
        const __nv_bfloat16* base = (region == 0) ? ahi : (region == 1) ? alo
                                  : (region == 2) ? whi : wlo;
        int grow = ((region < 2) ? m0 : n0) + r;
        gsrc[i] = base + (size_t)grow * KD + v * 8;
        sdst[i] = region * (128 * RS) + r * RS + v * 16;
    }

    float acc[4][4][4];
    #pragma unroll
    for (int mt = 0; mt < 4; mt++)
        #pragma unroll
        for (int nt = 0; nt < 4; nt++)
            #pragma unroll
            for (int e = 0; e < 4; e++) acc[mt][nt][e] = 0.f;

    uint4 st[8];
    #pragma unroll
    for (int i = 0; i < 8; i++) { st[i] = *(const uint4*)gsrc[i]; gsrc[i] += 32; }

    const int arow = lane & 15, abyte = (lane >> 4) * 16;
    const int brow = lane & 7,  bbyte = ((lane >> 3) & 1) * 16;

    for (int kc = 0; kc < KD / 32; kc++) {
        __syncthreads();
        #pragma unroll
        for (int i = 0; i < 8; i++) *(uint4*)(smem + sdst[i]) = st[i];
        __syncthreads();
        if (kc + 1 < KD / 32) {
            #pragma unroll
            for (int i = 0; i < 8; i++) { st[i] = *(const uint4*)gsrc[i]; gsrc[i] += 32; }
        }
        #pragma unroll
        for (int ks = 0; ks < 2; ks++) {
            uint32_t ah[4][4], al[4][4], bh[4][2], bl[4][2];
            #pragma unroll
            for (int mt = 0; mt < 4; mt++) {
                uint32_t aaddr = sb + (wm + mt * 16 + arow) * RS + ks * 32 + abyte;
                ldsm4(ah[mt], aaddr);
                ldsm4(al[mt], aaddr + 128 * RS);
            }
            #pragma unroll
            for (int nt = 0; nt < 4; nt++) {
                uint32_t baddr = sb + 2 * 128 * RS + (wn + nt * 8 + brow) * RS + ks * 32 + bbyte;
                ldsm2(bh[nt], baddr);
                ldsm2(bl[nt], baddr + 128 * RS);
            }
            #pragma unroll
            for (int mt = 0; mt < 4; mt++)
                #pragma unroll
                for (int nt = 0; nt < 4; nt++) {
                    mma_bf16(acc[mt][nt], ah[mt], bh[nt]);
                    mma_bf16(acc[mt][nt], ah[mt], bl[nt]);
                    mma_bf16(acc[mt][nt], al[mt], bh[nt]);
                }
        }
    }

    // epilogue: c0,c1 -> row lane/4, cols 2*(lane%4)+{0,1}; c2,c3 -> row+8
    #pragma unroll
    for (int mt = 0; mt < 4; mt++) {
        int row0 = m0 + wm + mt * 16 + (lane >> 2);
        #pragma unroll
        for (int nt = 0; nt < 4; nt++) {
            int col = n0 + wn + nt * 8 + (lane & 3) * 2;
            float2 bv = *(const float2*)&bias[col];
            float2 o0, o1;
            o0.x = acc[mt][nt][0] + bv.x; o0.y = acc[mt][nt][1] + bv.y;
            o1.x = acc[mt][nt][2] + bv.x; o1.y = acc[mt][nt][3] + bv.y;
            *(float2*)&C[(size_t)row0 * N3D + col] = o0;
            *(float2*)&C[(size_t)(row0 + 8) * N3D + col] = o1;
        }
    }
}

// ---------------------------------------------------------------------------
// Attention over NT tokens for one (b, fixedaxis, h). K/V resident in smem.
// R=4 query rows per warp pass, f32x2 packed accumulation.
// ---------------------------------------------------------------------------
template<int NT, int KPL>
__global__ void attn_kernel(const float* __restrict__ qkv, float* __restrict__ out) {
    extern __shared__ float fsmem[];
    float* kt = fsmem;
    float* vs = kt + NT * 64;
    float* qs = vs + NT * 64;
    float* ps = qs + 8 * 4 * 64;

    const int tid = threadIdx.x;
    const int bid = blockIdx.x;
    const int h = bid & 7;
    int qbase, qstride, obase, ostride;
    if (NT == 256) {
        int s = (bid >> 3) & 63;
        int b = bid >> 9;
        int tok0 = (b * 64 + s) * 256;
        qbase = tok0 * 1536 + h * 64;  qstride = 1536;
        obase = tok0 * 512 + h * 64;   ostride = 512;
    } else {
        int l = (bid >> 3) & 255;
        int b = bid >> 11;
        int tok0 = b * 16384 + l;
        qbase = tok0 * 1536 + h * 64;  qstride = 256 * 1536;
        obase = tok0 * 512 + h * 64;   ostride = 256 * 512;
    }

    for (int idx = tid; idx < NT * 64; idx += 256) {
        int j = idx >> 6, c = idx & 63;
        int g = qbase + j * qstride + c;
        float kv = qkv[g + 512];
        float vv = qkv[g + 1024];
        int cg = c >> 2, ci = c & 3;
        kt[((cg * NT + j) << 2) + ci] = kv;
        vs[idx] = vv;
    }
    __syncthreads();

    const int warp = tid >> 5, lane = tid & 31;
    float* qsw = qs + warp * 4 * 64;
    float* psw = ps + warp * 4 * NT;

    for (int r0 = warp * 4; r0 < NT; r0 += 32) {
        #pragma unroll
        for (int rr = 0; rr < 4; rr++)
            *(float2*)&qsw[rr * 64 + 2 * lane] =
                *(const float2*)&qkv[qbase + (r0 + rr) * qstride + 2 * lane];
        __syncwarp();

        uint64_t s2[4][KPL];
        #pragma unroll
        for (int rr = 0; rr < 4; rr++)
            #pragma unroll
            for (int kk = 0; kk < KPL; kk++) s2[rr][kk] = 0ull;

        #pragma unroll
        for (int cg = 0; cg < 16; cg++) {
            uint64_t q2[4][2];
            #pragma unroll
            for (int rr = 0; rr < 4; rr++) {
                ulonglong2 t = *(const ulonglong2*)&qsw[rr * 64 + cg * 4];
                q2[rr][0] = t.x; q2[rr][1] = t.y;
            }
            #pragma unroll
            for (int kk = 0; kk < KPL; kk++) {
                ulonglong2 kv = *(const ulonglong2*)&kt[(cg * NT + lane + kk * 32) << 2];
                #pragma unroll
                for (int rr = 0; rr < 4; rr++) {
                    fma2(s2[rr][kk], q2[rr][0], kv.x);
                    fma2(s2[rr][kk], q2[rr][1], kv.y);
                }
            }
        }

        float inv[4];
        #pragma unroll
        for (int rr = 0; rr < 4; rr++) {
            float s[KPL];
            #pragma unroll
            for (int kk = 0; kk < KPL; kk++) {
                float2 p = unpack2(s2[rr][kk]);
                s[kk] = p.x + p.y;
            }
            float mx = s[0];
            #pragma unroll
            for (int kk = 1; kk < KPL; kk++) mx = fmaxf(mx, s[kk]);
            #pragma unroll
            for (int o = 16; o > 0; o >>= 1) mx = fmaxf(mx, __shfl_xor_sync(0xffffffffu, mx, o));
            float sum = 0.f;
            #pragma unroll
            for (int kk = 0; kk < KPL; kk++) { s[kk] = __expf(s[kk] - mx); sum += s[kk]; }
            #pragma unroll
            for (int o = 16; o > 0; o >>= 1) sum += __shfl_xor_sync(0xffffffffu, sum, o);
            #pragma unroll
            for (int kk = 0; kk < KPL; kk++) psw[rr * NT + lane + kk * 32] = s[kk];
            inv[rr] = 1.f / sum;
        }
        __syncwarp();

        uint64_t acc[4] = {0ull, 0ull, 0ull, 0ull};
        #pragma unroll 2
        for (int j4 = 0; j4 < NT / 4; j4++) {
            const float* vrow = vs + j4 * 4 * 64 + 2 * lane;
            uint64_t v0 = *(const uint64_t*)(vrow);
            uint64_t v1 = *(const uint64_t*)(vrow + 64);
            uint64_t v2 = *(const uint64_t*)(vrow + 128);
            uint64_t v3 = *(const uint64_t*)(vrow + 192);
            #pragma unroll
            for (int rr = 0; rr < 4; rr++) {
                float4 p4 = *(const float4*)&psw[rr * NT + j4 * 4];
                fma2(acc[rr], pack2(p4.x, p4.x), v0);
                fma2(acc[rr], pack2(p4.y, p4.y), v1);
                fma2(acc[rr], pack2(p4.z, p4.z), v2);
                fma2(acc[rr], pack2(p4.w, p4.w), v3);
            }
        }
        #pragma unroll
        for (int rr = 0; rr < 4; rr++) {
            float2 o2 = unpack2(acc[rr]);
            o2.x *= inv[rr]; o2.y *= inv[rr];
            *(float2*)&out[obase + (size_t)(r0 + rr) * ostride + 2 * lane] = o2;
        }
        __syncwarp();
    }
}

// ---------------------------------------------------------------------------
// out = LayerNorm(a + b) * g + beta, D=512, one warp per row
// ---------------------------------------------------------------------------
__global__ void add_ln(const float* __restrict__ a, const float* __restrict__ b,
                       const float* __restrict__ g, const float* __restrict__ be,
                       float* __restrict__ out) {
    int row = blockIdx.x * 8 + (threadIdx.x >> 5);
    int lane = threadIdx.x & 31;
    const float* pa = a + (size_t)row * 512;
    const float* pb = b + (size_t)row * 512;
    float v[16];
    float sum = 0.f;
    #pragma unroll
    for (int i = 0; i < 4; i++) {
        int c = lane * 4 + i * 128;
        float4 x = *(const float4*)&pa[c];
        float4 y = *(const float4*)&pb[c];
        v[i*4+0] = x.x + y.x; v[i*4+1] = x.y + y.y;
        v[i*4+2] = x.z + y.z; v[i*4+3] = x.w + y.w;
        sum += v[i*4+0] + v[i*4+1] + v[i*4+2] + v[i*4+3];
    }
    #pragma unroll
    for (int o = 16; o > 0; o >>= 1) sum += __shfl_xor_sync(0xffffffffu, sum, o);
    float mu = sum * (1.f / 512.f);
    float var = 0.f;
    #pragma unroll
    for (int i = 0; i < 16; i++) { float d = v[i] - mu; var += d * d; }
    #pragma unroll
    for (int o = 16; o > 0; o >>= 1) var += __shfl_xor_sync(0xffffffffu, var, o);
    float rstd = rsqrtf(var * (1.f / 512.f) + 1e-5f);
    float* po = out + (size_t)row * 512;
    #pragma unroll
    for (int i = 0; i < 4; i++) {
        int c = lane * 4 + i * 128;
        float4 gg = *(const float4*)&g[c];
        float4 bb = *(const float4*)&be[c];
        float4 o4;
        o4.x = (v[i*4+0] - mu) * rstd * gg.x + bb.x;
        o4.y = (v[i*4+1] - mu) * rstd * gg.y + bb.y;
        o4.z = (v[i*4+2] - mu) * rstd * gg.z + bb.z;
        o4.w = (v[i*4+3] - mu) * rstd * gg.w + bb.w;
        *(float4*)&po[c] = o4;
    }
}

// ---------------------------------------------------------------------------

extern "C" void kernel_launch(void* const* d_in, const int* in_sizes, int n_in,
                              void* d_out, int out_size) {
    const float* x     = (const float*)d_in[0];
    const float* w_row = (const float*)d_in[1];
    const float* b_row = (const float*)d_in[2];
    const float* w_col = (const float*)d_in[3];
    const float* b_col = (const float*)d_in[4];
    const float* g1    = (const float*)d_in[5];
    const float* be1   = (const float*)d_in[6];
    const float* g2    = (const float*)d_in[7];
    const float* be2   = (const float*)d_in[8];
    float* out = (float*)d_out;

    float *qkv, *attn, *out1;
    __nv_bfloat16 *ahi, *alo, *whi, *wlo;
    cudaGetSymbolAddress((void**)&qkv,  g_qkv);
    cudaGetSymbolAddress((void**)&attn, g_attn);
    cudaGetSymbolAddress((void**)&out1, g_out1);
    cudaGetSymbolAddress((void**)&ahi,  g_ahi);
    cudaGetSymbolAddress((void**)&alo,  g_alo);
    cudaGetSymbolAddress((void**)&whi,  g_whi);
    cudaGetSymbolAddress((void**)&wlo,  g_wlo);

    const int smem_row = (256 * 64 * 2 + 8 * 4 * 64 + 8 * 4 * 256) * 4;
    const int smem_col = (64 * 64 * 2 + 8 * 4 * 64 + 8 * 4 * 64) * 4;
    cudaFuncSetAttribute(attn_kernel<256, 8>,
                         cudaFuncAttributeMaxDynamicSharedMemorySize, smem_row);
    cudaFuncSetAttribute(attn_kernel<64, 2>,
                         cudaFuncAttributeMaxDynamicSharedMemorySize, smem_col);

    const int n4x = M_TOK * KD / 4;
    const int n4w = N3D * KD / 4;
    dim3 ggrid(N3D / 128, M_TOK / 128);   // (12, 256)

    split_bf16<<<(n4x + 255) / 256, 256>>>(x, ahi, alo, n4x);
    split_bf16<<<(n4w + 255) / 256, 256>>>(w_row, whi, wlo, n4w);
    gemm_mma<<<ggrid, 256>>>(ahi, alo, whi, wlo, b_row, qkv);
    attn_kernel<256, 8><<<1024, 256, smem_row>>>(qkv, attn);
    add_ln<<<M_TOK / 8, 256>>>(x, attn, g1, be1, out1);

    split_bf16<<<(n4x + 255) / 256, 256>>>(out1, ahi, alo, n4x);
    split_bf16<<<(n4w + 255) / 256, 256>>>(w_col, whi, wlo, n4w);
    gemm_mma<<<ggrid, 256>>>(ahi, alo, whi, wlo, b_col, qkv);
    attn_kernel<64, 2><<<4096, 256, smem_col>>>(qkv, attn);
    add_ln<<<M_TOK / 8, 256>>>(out1, attn, g2, be2, out);
}

// round 5
// speedup vs baseline: 2.4206x; 1.2517x over previous
#include <cuda_runtime.h>
#include <cuda_bf16.h>
#include <math.h>
#include <cstdint>

// AxialSelfAttention2d: B=2,S=64,L=256,H=8,C=64,D=512
// Projections AND attention via mma.sync bf16 hi/lo split (base-ISA tensor
// cores; tcgen05 unavailable: harness targets sm_103 without 'a').
// Attention is flash-style with online softmax, fp32 accumulators.

#define M_TOK 32768
#define N3D 1536
#define KD 512

__device__ float g_qkv[(size_t)M_TOK * N3D];
__device__ float g_attn[(size_t)M_TOK * 512];
__device__ float g_out1[(size_t)M_TOK * 512];
__device__ __nv_bfloat16 g_ahi[(size_t)M_TOK * KD];
__device__ __nv_bfloat16 g_alo[(size_t)M_TOK * KD];
__device__ __nv_bfloat16 g_whi[(size_t)N3D * KD];
__device__ __nv_bfloat16 g_wlo[(size_t)N3D * KD];

// ---------------------------------------------------------------------------
// helpers
// ---------------------------------------------------------------------------
__device__ __forceinline__ uint32_t smem_u32(const void* p) {
    uint32_t a;
    asm("{ .reg .u64 t; cvta.to.shared.u64 t, %1; cvt.u32.u64 %0, t; }" : "=r"(a) : "l"(p));
    return a;
}
__device__ __forceinline__ void ldsm4(uint32_t* r, uint32_t a) {
    asm volatile("ldmatrix.sync.aligned.m8n8.x4.shared.b16 {%0,%1,%2,%3}, [%4];"
        : "=r"(r[0]), "=r"(r[1]), "=r"(r[2]), "=r"(r[3]) : "r"(a));
}
__device__ __forceinline__ void ldsm2(uint32_t* r, uint32_t a) {
    asm volatile("ldmatrix.sync.aligned.m8n8.x2.shared.b16 {%0,%1}, [%2];"
        : "=r"(r[0]), "=r"(r[1]) : "r"(a));
}
__device__ __forceinline__ void ldsm2t(uint32_t* r, uint32_t a) {
    asm volatile("ldmatrix.sync.aligned.m8n8.x2.trans.shared.b16 {%0,%1}, [%2];"
        : "=r"(r[0]), "=r"(r[1]) : "r"(a));
}
__device__ __forceinline__ void mma_bf16(float* c, const uint32_t* a, const uint32_t* b) {
    asm volatile("mma.sync.aligned.m16n8k16.row.col.f32.bf16.bf16.f32 "
        "{%0,%1,%2,%3}, {%4,%5,%6,%7}, {%8,%9}, {%0,%1,%2,%3};"
        : "+f"(c[0]), "+f"(c[1]), "+f"(c[2]), "+f"(c[3])
        : "r"(a[0]), "r"(a[1]), "r"(a[2]), "r"(a[3]), "r"(b[0]), "r"(b[1]));
}
// pack two floats to bf16x2 (lo = first arg in low half)
__device__ __forceinline__ uint32_t packbf(float lo, float hi) {
    uint32_t r;
    asm("cvt.rn.bf16x2.f32 %0, %1, %2;" : "=r"(r) : "f"(hi), "f"(lo));
    return r;
}
// recover the two bf16 hi-parts of a packed word as floats
__device__ __forceinline__ float2 bfhi2f(uint32_t w) {
    float2 r;
    r.x = __uint_as_float(w << 16);
    r.y = __uint_as_float(w & 0xffff0000u);
    return r;
}

// ---------------------------------------------------------------------------
// hi/lo bf16 split: hi = bf16(a), lo = bf16(a - float(hi))
// ---------------------------------------------------------------------------
__global__ void split_bf16(const float* __restrict__ in, __nv_bfloat16* __restrict__ hi,
                           __nv_bfloat16* __restrict__ lo, int n4) {
    int i = blockIdx.x * 256 + threadIdx.x;
    if (i >= n4) return;
    float4 v = ((const float4*)in)[i];
    uint32_t h0 = packbf(v.x, v.y), h1 = packbf(v.z, v.w);
    float2 f0 = bfhi2f(h0), f1 = bfhi2f(h1);
    ((uint32_t*)hi)[2*i]   = h0;
    ((uint32_t*)hi)[2*i+1] = h1;
    ((uint32_t*)lo)[2*i]   = packbf(v.x - f0.x, v.y - f0.y);
    ((uint32_t*)lo)[2*i+1] = packbf(v.z - f1.x, v.w - f1.y);
}

// ---------------------------------------------------------------------------
// GEMM via mma.sync: C[M,1536] = (Ahi+Alo)(Whi+Wlo)^T + bias (3 products)
// CTA 128x128, 8 warps (2m x 4n), warp tile 64x32, K staged 32 per iter.
// ---------------------------------------------------------------------------
#define RS 80

__global__ __launch_bounds__(256, 1)
void gemm_mma(const __nv_bfloat16* __restrict__ ahi, const __nv_bfloat16* __restrict__ alo,
              const __nv_bfloat16* __restrict__ whi, const __nv_bfloat16* __restrict__ wlo,
              const float* __restrict__ bias, float* __restrict__ C) {
    __shared__ char smem[4 * 128 * RS];
    const uint32_t sb = smem_u32(smem);
    const int tid = threadIdx.x;
    const int lane = tid & 31, warp = tid >> 5;
    const int wm = (warp >> 2) * 64;
    const int wn = (warp & 3) * 32;
    const int m0 = blockIdx.y * 128;
    const int n0 = blockIdx.x * 128;

    const __nv_bfloat16* gsrc[8];
    uint32_t sdst[8];
    #pragma unroll
    for (int i = 0; i < 8; i++) {
        int f = tid + i * 256;
        int region = f >> 9;
        int r = (f & 511) >> 2, v = f & 3;
        const __nv_bfloat16* base = (region == 0) ? ahi : (region == 1) ? alo
                                  : (region == 2) ? whi : wlo;
        int grow = ((region < 2) ? m0 : n0) + r;
        gsrc[i] = base + (size_t)grow * KD + v * 8;
        sdst[i] = region * (128 * RS) + r * RS + v * 16;
    }

    float acc[4][4][4];
    #pragma unroll
    for (int mt = 0; mt < 4; mt++)
        #pragma unroll
        for (int nt = 0; nt < 4; nt++)
            #pragma unroll
            for (int e = 0; e < 4; e++) acc[mt][nt][e] = 0.f;

    uint4 st[8];
    #pragma unroll
    for (int i = 0; i < 8; i++) { st[i] = *(const uint4*)gsrc[i]; gsrc[i] += 32; }

    const int arow = lane & 15, abyte = (lane >> 4) * 16;
    const int brow = lane & 7,  bbyte = ((lane >> 3) & 1) * 16;

    for (int kc = 0; kc < KD / 32; kc++) {
        __syncthreads();
        #pragma unroll
        for (int i = 0; i < 8; i++) *(uint4*)(smem + sdst[i]) = st[i];
        __syncthreads();
        if (kc + 1 < KD / 32) {
            #pragma unroll
            for (int i = 0; i < 8; i++) { st[i] = *(const uint4*)gsrc[i]; gsrc[i] += 32; }
        }
        #pragma unroll
        for (int ks = 0; ks < 2; ks++) {
            uint32_t ah[4][4], al[4][4], bh[4][2], bl[4][2];
            #pragma unroll
            for (int mt = 0; mt < 4; mt++) {
                uint32_t aaddr = sb + (wm + mt * 16 + arow) * RS + ks * 32 + abyte;
                ldsm4(ah[mt], aaddr);
                ldsm4(al[mt], aaddr + 128 * RS);
            }
            #pragma unroll
            for (int nt = 0; nt < 4; nt++) {
                uint32_t baddr = sb + 2 * 128 * RS + (wn + nt * 8 + brow) * RS + ks * 32 + bbyte;
                ldsm2(bh[nt], baddr);
                ldsm2(bl[nt], baddr + 128 * RS);
            }
            #pragma unroll
            for (int mt = 0; mt < 4; mt++)
                #pragma unroll
                for (int nt = 0; nt < 4; nt++) {
                    mma_bf16(acc[mt][nt], ah[mt], bh[nt]);
                    mma_bf16(acc[mt][nt], ah[mt], bl[nt]);
                    mma_bf16(acc[mt][nt], al[mt], bh[nt]);
                }
        }
    }

    #pragma unroll
    for (int mt = 0; mt < 4; mt++) {
        int row0 = m0 + wm + mt * 16 + (lane >> 2);
        #pragma unroll
        for (int nt = 0; nt < 4; nt++) {
            int col = n0 + wn + nt * 8 + (lane & 3) * 2;
            float2 bv = *(const float2*)&bias[col];
            float2 o0, o1;
            o0.x = acc[mt][nt][0] + bv.x; o0.y = acc[mt][nt][1] + bv.y;
            o1.x = acc[mt][nt][2] + bv.x; o1.y = acc[mt][nt][3] + bv.y;
            *(float2*)&C[(size_t)row0 * N3D + col] = o0;
            *(float2*)&C[(size_t)(row0 + 8) * N3D + col] = o1;
        }
    }
}

// ---------------------------------------------------------------------------
// Flash attention via mma.sync, bf16 hi/lo split.
// ISROW: CTA = (b,s,h), 256 keys (4 key tiles), 8 warps x 2 passes x 16 q-rows.
// !ISROW: CTA = (b,l,head-pair), 64 keys (1 tile), warp (w>>2)=local head,
//         (w&3)=mtile, 1 pass x 16 q-rows.
// K/V staged in smem as bf16 hi/lo (144B row stride, conflict-free ldmatrix).
// QK: 3 products (qh*kh + qh*kl + ql*kh). PV: ph*vh + ph*vl + pl*vh, with
// V^T fragments via ldmatrix.trans. Online softmax, fp32 accum, no QK scale.
// ---------------------------------------------------------------------------
template<bool ISROW>
__global__ __launch_bounds__(256, 1)
void attn_mma(const float* __restrict__ qkv, float* __restrict__ out) {
    constexpr int NK   = ISROW ? 256 : 64;       // keys
    constexpr int NKT  = NK / 64;                // key tiles
    constexpr int NPASS = ISROW ? 2 : 1;
    constexpr int MATB = NK * 144;               // bytes per K/V matrix
    extern __shared__ char sm[];
    const uint32_t sb = smem_u32(sm);
    const int tid = threadIdx.x, lane = tid & 31, warp = tid >> 5;
    const int bid = blockIdx.x;

    int b, h;
    long tok0 = 0;       // row mode: first token of this (b,s) line
    int lcoord = 0;      // col mode: fixed l
    uint32_t kvb;        // byte offset of this warp's KHI region
    uint32_t QHIo;

    if (ISROW) {
        h = bid & 7;
        int s = (bid >> 3) & 63;
        b = bid >> 9;
        tok0 = (long)(b * 64 + s) * 256;
        kvb = 0;
        QHIo = 4 * MATB;
    } else {
        int hp = bid & 3;
        lcoord = (bid >> 2) & 255;
        b = bid >> 10;
        int lh = warp >> 2;
        h = hp * 2 + lh;
        kvb = (uint32_t)lh * 4 * MATB;
        QHIo = 8 * MATB;
    }

    // ---- stage K/V (fp32 gmem -> bf16 hi/lo smem) ----
    if (ISROW) {
        for (int idx = tid; idx < NK * 32; idx += 256) {
            int j = idx >> 5, c2 = idx & 31;
            long g = (tok0 + j) * 1536 + h * 64 + c2 * 2;
            float2 kf = *(const float2*)&qkv[g + 512];
            float2 vf = *(const float2*)&qkv[g + 1024];
            uint32_t kw = packbf(kf.x, kf.y);
            uint32_t vw = packbf(vf.x, vf.y);
            float2 kh = bfhi2f(kw), vh = bfhi2f(vw);
            uint32_t off = j * 144 + c2 * 4;
            *(uint32_t*)(sm + off)            = kw;
            *(uint32_t*)(sm + MATB + off)     = packbf(kf.x - kh.x, kf.y - kh.y);
            *(uint32_t*)(sm + 2 * MATB + off) = vw;
            *(uint32_t*)(sm + 3 * MATB + off) = packbf(vf.x - vh.x, vf.y - vh.y);
        }
    } else {
        int hp = bid & 3;
        for (int idx = tid; idx < 2 * 64 * 32; idx += 256) {
            int lh = idx >> 11, j = (idx >> 5) & 63, c2 = idx & 31;
            long g = ((long)(b * 64 + j) * 256 + lcoord) * 1536 + (hp * 2 + lh) * 64 + c2 * 2;
            float2 kf = *(const float2*)&qkv[g + 512];
            float2 vf = *(const float2*)&qkv[g + 1024];
            uint32_t kw = packbf(kf.x, kf.y);
            uint32_t vw = packbf(vf.x, vf.y);
            float2 kh = bfhi2f(kw), vh = bfhi2f(vw);
            uint32_t base = (uint32_t)lh * 4 * MATB;
            uint32_t off = j * 144 + c2 * 4;
            *(uint32_t*)(sm + base + off)            = kw;
            *(uint32_t*)(sm + base + MATB + off)     = packbf(kf.x - kh.x, kf.y - kh.y);
            *(uint32_t*)(sm + base + 2 * MATB + off) = vw;
            *(uint32_t*)(sm + base + 3 * MATB + off) = packbf(vf.x - vh.x, vf.y - vh.y);
        }
    }
    __syncthreads();

    const uint32_t qwb = QHIo + warp * 2304;   // 16 rows x 144B per warp

    for (int p = 0; p < NPASS; p++) {
        const int qrow0 = ISROW ? (p * 8 + warp) * 16 : (warp & 3) * 16;

        // ---- stage this warp's 16 Q rows (hi/lo) ----
        for (int f = lane; f < 256; f += 32) {
            int row = f >> 4, c4 = f & 15;
            long ti = ISROW ? (tok0 + qrow0 + row)
                            : ((long)(b * 64 + qrow0 + row) * 256 + lcoord);
            float4 qv = *(const float4*)&qkv[ti * 1536 + h * 64 + c4 * 4];
            uint32_t w0 = packbf(qv.x, qv.y), w1 = packbf(qv.z, qv.w);
            float2 f0 = bfhi2f(w0), f1 = bfhi2f(w1);
            uint32_t* d = (uint32_t*)(sm + qwb + row * 144 + c4 * 8);
            d[0] = w0; d[1] = w1;
            uint32_t* dl = (uint32_t*)(sm + qwb + 8 * 2304 + row * 144 + c4 * 8);
            dl[0] = packbf(qv.x - f0.x, qv.y - f0.y);
            dl[1] = packbf(qv.z - f1.x, qv.w - f1.y);
        }
        __syncwarp();

        // ---- Q fragments (kept across key tiles) ----
        uint32_t qh[4][4], ql[4][4];
        #pragma unroll
        for (int kt = 0; kt < 4; kt++) {
            uint32_t qa = sb + qwb + (lane & 15) * 144 + kt * 32 + (lane >> 4) * 16;
            ldsm4(qh[kt], qa);
            ldsm4(ql[kt], qa + 8 * 2304);
        }

        float O[8][4];
        #pragma unroll
        for (int nv = 0; nv < 8; nv++)
            #pragma unroll
            for (int e = 0; e < 4; e++) O[nv][e] = 0.f;
        float m0 = -1e30f, m1 = -1e30f, l0 = 0.f, l1 = 0.f;

        for (int t = 0; t < NKT; t++) {
            const int j0 = t * 64;
            float S[8][4];
            #pragma unroll
            for (int nt = 0; nt < 8; nt++)
                #pragma unroll
                for (int e = 0; e < 4; e++) S[nt][e] = 0.f;

            // ---- QK^T ----
            #pragma unroll
            for (int c = 0; c < 4; c++) {
                #pragma unroll
                for (int nt = 0; nt < 8; nt++) {
                    uint32_t ka = sb + kvb + (j0 + nt * 8 + (lane & 7)) * 144
                                + c * 32 + ((lane >> 3) & 1) * 16;
                    uint32_t kh2[2], kl2[2];
                    ldsm2(kh2, ka);
                    ldsm2(kl2, ka + MATB);
                    mma_bf16(S[nt], qh[c], kh2);
                    mma_bf16(S[nt], qh[c], kl2);
                    mma_bf16(S[nt], ql[c], kh2);
                }
            }

            // ---- online softmax (rows lane/4 and lane/4+8; quad = lanes xor 1,2) ----
            float mx0 = S[0][0], mx1 = S[0][2];
            #pragma unroll
            for (int nt = 0; nt < 8; nt++) {
                mx0 = fmaxf(mx0, fmaxf(S[nt][0], S[nt][1]));
                mx1 = fmaxf(mx1, fmaxf(S[nt][2], S[nt][3]));
            }
            mx0 = fmaxf(mx0, __shfl_xor_sync(0xffffffffu, mx0, 1));
            mx0 = fmaxf(mx0, __shfl_xor_sync(0xffffffffu, mx0, 2));
            mx1 = fmaxf(mx1, __shfl_xor_sync(0xffffffffu, mx1, 1));
            mx1 = fmaxf(mx1, __shfl_xor_sync(0xffffffffu, mx1, 2));
            float mn0 = fmaxf(m0, mx0), mn1 = fmaxf(m1, mx1);
            float sc0 = __expf(m0 - mn0), sc1 = __expf(m1 - mn1);
            m0 = mn0; m1 = mn1;

            float sum0 = 0.f, sum1 = 0.f;
            #pragma unroll
            for (int nt = 0; nt < 8; nt++) {
                S[nt][0] = __expf(S[nt][0] - m0);
                S[nt][1] = __expf(S[nt][1] - m0);
                S[nt][2] = __expf(S[nt][2] - m1);
                S[nt][3] = __expf(S[nt][3] - m1);
                sum0 += S[nt][0] + S[nt][1];
                sum1 += S[nt][2] + S[nt][3];
            }
            sum0 += __shfl_xor_sync(0xffffffffu, sum0, 1);
            sum0 += __shfl_xor_sync(0xffffffffu, sum0, 2);
            sum1 += __shfl_xor_sync(0xffffffffu, sum1, 1);
            sum1 += __shfl_xor_sync(0xffffffffu, sum1, 2);
            l0 = l0 * sc0 + sum0;
            l1 = l1 * sc1 + sum1;
            #pragma unroll
            for (int nv = 0; nv < 8; nv++) {
                O[nv][0] *= sc0; O[nv][1] *= sc0;
                O[nv][2] *= sc1; O[nv][3] *= sc1;
            }

            // ---- P·V (P hi/lo within-lane repack; V^T via ldmatrix.trans) ----
            #pragma unroll
            for (int kp = 0; kp < 4; kp++) {
                uint32_t aph[4], apl[4];
                #pragma unroll
                for (int half = 0; half < 2; half++) {
                    const float* Sv = S[2 * kp + half];
                    uint32_t w0 = packbf(Sv[0], Sv[1]);
                    uint32_t w1 = packbf(Sv[2], Sv[3]);
                    float2 h0 = bfhi2f(w0), h1 = bfhi2f(w1);
                    aph[2 * half]     = w0;
                    aph[2 * half + 1] = w1;
                    apl[2 * half]     = packbf(Sv[0] - h0.x, Sv[1] - h0.y);
                    apl[2 * half + 1] = packbf(Sv[2] - h1.x, Sv[3] - h1.y);
                }
                // reorder: A frag = {m0k0, m1k0, m0k8, m1k8} = {w0(t), w1(t), w0(t+1), w1(t+1)}
                // built above as half0 -> regs0,1 ; half1 -> regs2,3  (correct)
                uint32_t vrow = (uint32_t)(j0 + kp * 16 + ((lane >> 3) & 1) * 8 + (lane & 7));
                #pragma unroll
                for (int nv = 0; nv < 8; nv++) {
                    uint32_t va = sb + kvb + 2 * MATB + vrow * 144 + nv * 16;
                    uint32_t vh2[2], vl2[2];
                    ldsm2t(vh2, va);
                    ldsm2t(vl2, va + MATB);
                    mma_bf16(O[nv], aph, vh2);
                    mma_bf16(O[nv], aph, vl2);
                    mma_bf16(O[nv], apl, vh2);
                }
            }
        }

        // ---- write out ----
        float inv0 = 1.f / l0, inv1 = 1.f / l1;
        int r = qrow0 + (lane >> 2);
        long t0 = ISROW ? (tok0 + r) : ((long)(b * 64 + r) * 256 + lcoord);
        long t1 = ISROW ? (tok0 + r + 8) : ((long)(b * 64 + r + 8) * 256 + lcoord);
        #pragma unroll
        for (int nv = 0; nv < 8; nv++) {
            int col = h * 64 + nv * 8 + (lane & 3) * 2;
            float2 o0, o1;
            o0.x = O[nv][0] * inv0; o0.y = O[nv][1] * inv0;
            o1.x = O[nv][2] * inv1; o1.y = O[nv][3] * inv1;
            *(float2*)&out[t0 * 512 + col] = o0;
            *(float2*)&out[t1 * 512 + col] = o1;
        }
        __syncwarp();
    }
}

// ---------------------------------------------------------------------------
// out = LayerNorm(a + b) * g + beta, D=512, one warp per row
// ---------------------------------------------------------------------------
__global__ void add_ln(const float* __restrict__ a, const float* __restrict__ b,
                       const float* __restrict__ g, const float* __restrict__ be,
                       float* __restrict__ out) {
    int row = blockIdx.x * 8 + (threadIdx.x >> 5);
    int lane = threadIdx.x & 31;
    const float* pa = a + (size_t)row * 512;
    const float* pb = b + (size_t)row * 512;
    float v[16];
    float sum = 0.f;
    #pragma unroll
    for (int i = 0; i < 4; i++) {
        int c = lane * 4 + i * 128;
        float4 x = *(const float4*)&pa[c];
        float4 y = *(const float4*)&pb[c];
        v[i*4+0] = x.x + y.x; v[i*4+1] = x.y + y.y;
        v[i*4+2] = x.z + y.z; v[i*4+3] = x.w + y.w;
        sum += v[i*4+0] + v[i*4+1] + v[i*4+2] + v[i*4+3];
    }
    #pragma unroll
    for (int o = 16; o > 0; o >>= 1) sum += __shfl_xor_sync(0xffffffffu, sum, o);
    float mu = sum * (1.f / 512.f);
    float var = 0.f;
    #pragma unroll
    for (int i = 0; i < 16; i++) { float d = v[i] - mu; var += d * d; }
    #pragma unroll
    for (int o = 16; o > 0; o >>= 1) var += __shfl_xor_sync(0xffffffffu, var, o);
    float rstd = rsqrtf(var * (1.f / 512.f) + 1e-5f);
    float* po = out + (size_t)row * 512;
    #pragma unroll
    for (int i = 0; i < 4; i++) {
        int c = lane * 4 + i * 128;
        float4 gg = *(const float4*)&g[c];
        float4 bb = *(const float4*)&be[c];
        float4 o4;
        o4.x = (v[i*4+0] - mu) * rstd * gg.x + bb.x;
        o4.y = (v[i*4+1] - mu) * rstd * gg.y + bb.y;
        o4.z = (v[i*4+2] - mu) * rstd * gg.z + bb.z;
        o4.w = (v[i*4+3] - mu) * rstd * gg.w + bb.w;
        *(float4*)&po[c] = o4;
    }
}

// ---------------------------------------------------------------------------

extern "C" void kernel_launch(void* const* d_in, const int* in_sizes, int n_in,
                              void* d_out, int out_size) {
    const float* x     = (const float*)d_in[0];
    const float* w_row = (const float*)d_in[1];
    const float* b_row = (const float*)d_in[2];
    const float* w_col = (const float*)d_in[3];
    const float* b_col = (const float*)d_in[4];
    const float* g1    = (const float*)d_in[5];
    const float* be1   = (const float*)d_in[6];
    const float* g2    = (const float*)d_in[7];
    const float* be2   = (const float*)d_in[8];
    float* out = (float*)d_out;

    float *qkv, *attn, *out1;
    __nv_bfloat16 *ahi, *alo, *whi, *wlo;
    cudaGetSymbolAddress((void**)&qkv,  g_qkv);
    cudaGetSymbolAddress((void**)&attn, g_attn);
    cudaGetSymbolAddress((void**)&out1, g_out1);
    cudaGetSymbolAddress((void**)&ahi,  g_ahi);
    cudaGetSymbolAddress((void**)&alo,  g_alo);
    cudaGetSymbolAddress((void**)&whi,  g_whi);
    cudaGetSymbolAddress((void**)&wlo,  g_wlo);

    // smem: row = 4 K/V mats (256x144) + Q hi/lo (2 x 8 x 16 x 144)
    const int smem_row = 4 * 256 * 144 + 2 * 8 * 16 * 144;   // 184320
    const int smem_col = 8 * 64 * 144 + 2 * 8 * 16 * 144;    // 110592
    cudaFuncSetAttribute(attn_mma<true>,
                         cudaFuncAttributeMaxDynamicSharedMemorySize, smem_row);
    cudaFuncSetAttribute(attn_mma<false>,
                         cudaFuncAttributeMaxDynamicSharedMemorySize, smem_col);

    const int n4x = M_TOK * KD / 4;
    const int n4w = N3D * KD / 4;
    dim3 ggrid(N3D / 128, M_TOK / 128);

    split_bf16<<<(n4x + 255) / 256, 256>>>(x, ahi, alo, n4x);
    split_bf16<<<(n4w + 255) / 256, 256>>>(w_row, whi, wlo, n4w);
    gemm_mma<<<ggrid, 256>>>(ahi, alo, whi, wlo, b_row, qkv);
    attn_mma<true><<<1024, 256, smem_row>>>(qkv, attn);
    add_ln<<<M_TOK / 8, 256>>>(x, attn, g1, be1, out1);

    split_bf16<<<(n4x + 255) / 256, 256>>>(out1, ahi, alo, n4x);
    split_bf16<<<(n4w + 255) / 256, 256>>>(w_col, whi, wlo, n4w);
    gemm_mma<<<ggrid, 256>>>(ahi, alo, whi, wlo, b_col, qkv);
    attn_mma<false><<<2048, 256, smem_col>>>(qkv, attn);
    add_ln<<<M_TOK / 8, 256>>>(out1, attn, g2, be2, out);
}

// round 6
// speedup vs baseline: 2.6670x; 1.1018x over previous
#include <cuda_runtime.h>
#include <cuda_bf16.h>
#include <math.h>
#include <cstdint>

// AxialSelfAttention2d: B=2,S=64,L=256,H=8,C=64,D=512
// Projections + attention on legacy mma.sync bf16 hi/lo split tensor cores.
// GEMM: cp.async 3-buffer pipeline, CTA 128x256, warp tile 64x64.

#define M_TOK 32768
#define N3D 1536
#define KD 512

__device__ float g_qkv[(size_t)M_TOK * N3D];
__device__ float g_attn[(size_t)M_TOK * 512];
__device__ float g_out1[(size_t)M_TOK * 512];
__device__ __nv_bfloat16 g_ahi[(size_t)M_TOK * KD];
__device__ __nv_bfloat16 g_alo[(size_t)M_TOK * KD];
__device__ __nv_bfloat16 g_whi[(size_t)N3D * KD];
__device__ __nv_bfloat16 g_wlo[(size_t)N3D * KD];

// ---------------------------------------------------------------------------
// helpers
// ---------------------------------------------------------------------------
__device__ __forceinline__ uint32_t smem_u32(const void* p) {
    uint32_t a;
    asm("{ .reg .u64 t; cvta.to.shared.u64 t, %1; cvt.u32.u64 %0, t; }" : "=r"(a) : "l"(p));
    return a;
}
__device__ __forceinline__ void ldsm4(uint32_t* r, uint32_t a) {
    asm volatile("ldmatrix.sync.aligned.m8n8.x4.shared.b16 {%0,%1,%2,%3}, [%4];"
        : "=r"(r[0]), "=r"(r[1]), "=r"(r[2]), "=r"(r[3]) : "r"(a));
}
__device__ __forceinline__ void ldsm2(uint32_t* r, uint32_t a) {
    asm volatile("ldmatrix.sync.aligned.m8n8.x2.shared.b16 {%0,%1}, [%2];"
        : "=r"(r[0]), "=r"(r[1]) : "r"(a));
}
__device__ __forceinline__ void ldsm2t(uint32_t* r, uint32_t a) {
    asm volatile("ldmatrix.sync.aligned.m8n8.x2.trans.shared.b16 {%0,%1}, [%2];"
        : "=r"(r[0]), "=r"(r[1]) : "r"(a));
}
__device__ __forceinline__ void mma_bf16(float* c, const uint32_t* a, const uint32_t* b) {
    asm volatile("mma.sync.aligned.m16n8k16.row.col.f32.bf16.bf16.f32 "
        "{%0,%1,%2,%3}, {%4,%5,%6,%7}, {%8,%9}, {%0,%1,%2,%3};"
        : "+f"(c[0]), "+f"(c[1]), "+f"(c[2]), "+f"(c[3])
        : "r"(a[0]), "r"(a[1]), "r"(a[2]), "r"(a[3]), "r"(b[0]), "r"(b[1]));
}
__device__ __forceinline__ uint32_t packbf(float lo, float hi) {
    uint32_t r;
    asm("cvt.rn.bf16x2.f32 %0, %1, %2;" : "=r"(r) : "f"(hi), "f"(lo));
    return r;
}
__device__ __forceinline__ float2 bfhi2f(uint32_t w) {
    float2 r;
    r.x = __uint_as_float(w << 16);
    r.y = __uint_as_float(w & 0xffff0000u);
    return r;
}
__device__ __forceinline__ void cpasync16(uint32_t dst, const void* src) {
    asm volatile("cp.async.cg.shared.global [%0], [%1], 16;" :: "r"(dst), "l"(src));
}
#define CP_COMMIT() asm volatile("cp.async.commit_group;" ::: "memory")
#define CP_WAIT1()  asm volatile("cp.async.wait_group 1;" ::: "memory")

// ---------------------------------------------------------------------------
// hi/lo bf16 split: hi = bf16(a), lo = bf16(a - float(hi))
// ---------------------------------------------------------------------------
__global__ void split_bf16(const float* __restrict__ in, __nv_bfloat16* __restrict__ hi,
                           __nv_bfloat16* __restrict__ lo, int n4) {
    int i = blockIdx.x * 256 + threadIdx.x;
    if (i >= n4) return;
    float4 v = ((const float4*)in)[i];
    uint32_t h0 = packbf(v.x, v.y), h1 = packbf(v.z, v.w);
    float2 f0 = bfhi2f(h0), f1 = bfhi2f(h1);
    ((uint32_t*)hi)[2*i]   = h0;
    ((uint32_t*)hi)[2*i+1] = h1;
    ((uint32_t*)lo)[2*i]   = packbf(v.x - f0.x, v.y - f0.y);
    ((uint32_t*)lo)[2*i+1] = packbf(v.z - f1.x, v.w - f1.y);
}

// ---------------------------------------------------------------------------
// GEMM via mma.sync: C[M,1536] = (Ahi+Alo)(Whi+Wlo)^T + bias (3 products)
// CTA 128x256, 8 warps (2m x 4n), warp tile 64x64.
// cp.async 3-buffer pipeline, K staged 32 per chunk, 1 syncthreads per chunk.
// ---------------------------------------------------------------------------
#define GRS 80                       // smem row stride (64 data + 16 pad)
#define ST_AHI 0
#define ST_ALO (128 * GRS)           // 10240
#define ST_WHI (2 * 128 * GRS)       // 20480
#define ST_WLO (ST_WHI + 256 * GRS)  // 40960
#define STG_SZ (ST_WHI + 2 * 256 * GRS)  // 61440
#define GEMM_SMEM (3 * STG_SZ)           // 184320

__global__ __launch_bounds__(256, 1)
void gemm_mma(const __nv_bfloat16* __restrict__ ahi, const __nv_bfloat16* __restrict__ alo,
              const __nv_bfloat16* __restrict__ whi, const __nv_bfloat16* __restrict__ wlo,
              const float* __restrict__ bias, float* __restrict__ C) {
    extern __shared__ char smg[];
    const uint32_t sb = smem_u32(smg);
    const int tid = threadIdx.x;
    const int lane = tid & 31, warp = tid >> 5;
    const int wm = (warp >> 2) * 64;
    const int wn = (warp & 3) * 64;
    const int m0 = blockIdx.y * 128;
    const int n0 = blockIdx.x * 256;

    // 3072 16B vectors per stage, 12 per thread
    const __nv_bfloat16* gsrc[12];
    uint32_t dstoff[12];
    #pragma unroll
    for (int i = 0; i < 12; i++) {
        int f = tid + i * 256;
        int v = f & 3;
        if (f < 1024) {                 // A hi | A lo
            int r = (f & 511) >> 2;
            gsrc[i] = ((f < 512) ? ahi : alo) + (size_t)(m0 + r) * KD + v * 8;
            dstoff[i] = ((f < 512) ? ST_AHI : ST_ALO) + r * GRS + v * 16;
        } else {                        // W hi | W lo
            int r = (f & 1023) >> 2;
            gsrc[i] = ((f < 2048) ? whi : wlo) + (size_t)(n0 + r) * KD + v * 8;
            dstoff[i] = ((f < 2048) ? ST_WHI : ST_WLO) + r * GRS + v * 16;
        }
    }

    #define GEMM_ISSUE(kc) do { \
        uint32_t _s = sb + ((kc) % 3) * STG_SZ; \
        _Pragma("unroll") \
        for (int i = 0; i < 12; i++) \
            cpasync16(_s + dstoff[i], gsrc[i] + (size_t)(kc) * 32); \
        CP_COMMIT(); \
    } while (0)

    GEMM_ISSUE(0);
    GEMM_ISSUE(1);

    float acc[4][8][4];
    #pragma unroll
    for (int mt = 0; mt < 4; mt++)
        #pragma unroll
        for (int nt = 0; nt < 8; nt++)
            #pragma unroll
            for (int e = 0; e < 4; e++) acc[mt][nt][e] = 0.f;

    const uint32_t arow = (lane & 15), abyte = (lane >> 4) * 16;
    const uint32_t brow = (lane & 7) + ((lane >> 4) << 3), bbyte = ((lane >> 3) & 1) * 16;

    for (int kc = 0; kc < KD / 32; kc++) {
        CP_WAIT1();
        __syncthreads();
        if (kc + 2 < KD / 32) GEMM_ISSUE(kc + 2);

        const uint32_t st = sb + (kc % 3) * STG_SZ;
        #pragma unroll
        for (int ks = 0; ks < 2; ks++) {
            uint32_t ah[4][4], bh[4][4];
            #pragma unroll
            for (int mt = 0; mt < 4; mt++)
                ldsm4(ah[mt], st + ST_AHI + (wm + mt * 16 + arow) * GRS + ks * 32 + abyte);
            #pragma unroll
            for (int np = 0; np < 4; np++)
                ldsm4(bh[np], st + ST_WHI + (wn + np * 16 + brow) * GRS + ks * 32 + bbyte);
            #pragma unroll
            for (int mt = 0; mt < 4; mt++)
                #pragma unroll
                for (int nt = 0; nt < 8; nt++)
                    mma_bf16(acc[mt][nt], ah[mt], &bh[nt >> 1][(nt & 1) * 2]);

            uint32_t bl[4][4];
            #pragma unroll
            for (int np = 0; np < 4; np++)
                ldsm4(bl[np], st + ST_WLO + (wn + np * 16 + brow) * GRS + ks * 32 + bbyte);
            #pragma unroll
            for (int mt = 0; mt < 4; mt++)
                #pragma unroll
                for (int nt = 0; nt < 8; nt++)
                    mma_bf16(acc[mt][nt], ah[mt], &bl[nt >> 1][(nt & 1) * 2]);

            uint32_t al[4][4];
            #pragma unroll
            for (int mt = 0; mt < 4; mt++)
                ldsm4(al[mt], st + ST_ALO + (wm + mt * 16 + arow) * GRS + ks * 32 + abyte);
            #pragma unroll
            for (int mt = 0; mt < 4; mt++)
                #pragma unroll
                for (int nt = 0; nt < 8; nt++)
                    mma_bf16(acc[mt][nt], al[mt], &bh[nt >> 1][(nt & 1) * 2]);
        }
    }

    #pragma unroll
    for (int mt = 0; mt < 4; mt++) {
        int row0 = m0 + wm + mt * 16 + (lane >> 2);
        #pragma unroll
        for (int nt = 0; nt < 8; nt++) {
            int col = n0 + wn + nt * 8 + (lane & 3) * 2;
            float2 bv = *(const float2*)&bias[col];
            float2 o0, o1;
            o0.x = acc[mt][nt][0] + bv.x; o0.y = acc[mt][nt][1] + bv.y;
            o1.x = acc[mt][nt][2] + bv.x; o1.y = acc[mt][nt][3] + bv.y;
            *(float2*)&C[(size_t)row0 * N3D + col] = o0;
            *(float2*)&C[(size_t)(row0 + 8) * N3D + col] = o1;
        }
    }
}

// ---------------------------------------------------------------------------
// Flash attention via mma.sync, bf16 hi/lo split (unchanged from R5).
// ---------------------------------------------------------------------------
template<bool ISROW>
__global__ __launch_bounds__(256, 1)
void attn_mma(const float* __restrict__ qkv, float* __restrict__ out) {
    constexpr int NK   = ISROW ? 256 : 64;
    constexpr int NKT  = NK / 64;
    constexpr int NPASS = ISROW ? 2 : 1;
    constexpr int MATB = NK * 144;
    extern __shared__ char sm[];
    const uint32_t sb = smem_u32(sm);
    const int tid = threadIdx.x, lane = tid & 31, warp = tid >> 5;
    const int bid = blockIdx.x;

    int b, h;
    long tok0 = 0;
    int lcoord = 0;
    uint32_t kvb;
    uint32_t QHIo;

    if (ISROW) {
        h = bid & 7;
        int s = (bid >> 3) & 63;
        b = bid >> 9;
        tok0 = (long)(b * 64 + s) * 256;
        kvb = 0;
        QHIo = 4 * MATB;
    } else {
        int hp = bid & 3;
        lcoord = (bid >> 2) & 255;
        b = bid >> 10;
        int lh = warp >> 2;
        h = hp * 2 + lh;
        kvb = (uint32_t)lh * 4 * MATB;
        QHIo = 8 * MATB;
    }

    if (ISROW) {
        for (int idx = tid; idx < NK * 32; idx += 256) {
            int j = idx >> 5, c2 = idx & 31;
            long g = (tok0 + j) * 1536 + h * 64 + c2 * 2;
            float2 kf = *(const float2*)&qkv[g + 512];
            float2 vf = *(const float2*)&qkv[g + 1024];
            uint32_t kw = packbf(kf.x, kf.y);
            uint32_t vw = packbf(vf.x, vf.y);
            float2 kh = bfhi2f(kw), vh = bfhi2f(vw);
            uint32_t off = j * 144 + c2 * 4;
            *(uint32_t*)(sm + off)            = kw;
            *(uint32_t*)(sm + MATB + off)     = packbf(kf.x - kh.x, kf.y - kh.y);
            *(uint32_t*)(sm + 2 * MATB + off) = vw;
            *(uint32_t*)(sm + 3 * MATB + off) = packbf(vf.x - vh.x, vf.y - vh.y);
        }
    } else {
        int hp = bid & 3;
        for (int idx = tid; idx < 2 * 64 * 32; idx += 256) {
            int lh = idx >> 11, j = (idx >> 5) & 63, c2 = idx & 31;
            long g = ((long)(b * 64 + j) * 256 + lcoord) * 1536 + (hp * 2 + lh) * 64 + c2 * 2;
            float2 kf = *(const float2*)&qkv[g + 512];
            float2 vf = *(const float2*)&qkv[g + 1024];
            uint32_t kw = packbf(kf.x, kf.y);
            uint32_t vw = packbf(vf.x, vf.y);
            float2 kh = bfhi2f(kw), vh = bfhi2f(vw);
            uint32_t base = (uint32_t)lh * 4 * MATB;
            uint32_t off = j * 144 + c2 * 4;
            *(uint32_t*)(sm + base + off)            = kw;
            *(uint32_t*)(sm + base + MATB + off)     = packbf(kf.x - kh.x, kf.y - kh.y);
            *(uint32_t*)(sm + base + 2 * MATB + off) = vw;
            *(uint32_t*)(sm + base + 3 * MATB + off) = packbf(vf.x - vh.x, vf.y - vh.y);
        }
    }
    __syncthreads();

    const uint32_t qwb = QHIo + warp * 2304;

    for (int p = 0; p < NPASS; p++) {
        const int qrow0 = ISROW ? (p * 8 + warp) * 16 : (warp & 3) * 16;

        for (int f = lane; f < 256; f += 32) {
            int row = f >> 4, c4 = f & 15;
            long ti = ISROW ? (tok0 + qrow0 + row)
                            : ((long)(b * 64 + qrow0 + row) * 256 + lcoord);
            float4 qv = *(const float4*)&qkv[ti * 1536 + h * 64 + c4 * 4];
            uint32_t w0 = packbf(qv.x, qv.y), w1 = packbf(qv.z, qv.w);
            float2 f0 = bfhi2f(w0), f1 = bfhi2f(w1);
            uint32_t* d = (uint32_t*)(sm + qwb + row * 144 + c4 * 8);
            d[0] = w0; d[1] = w1;
            uint32_t* dl = (uint32_t*)(sm + qwb + 8 * 2304 + row * 144 + c4 * 8);
            dl[0] = packbf(qv.x - f0.x, qv.y - f0.y);
            dl[1] = packbf(qv.z - f1.x, qv.w - f1.y);
        }
        __syncwarp();

        uint32_t qh[4][4], ql[4][4];
        #pragma unroll
        for (int kt = 0; kt < 4; kt++) {
            uint32_t qa = sb + qwb + (lane & 15) * 144 + kt * 32 + (lane >> 4) * 16;
            ldsm4(qh[kt], qa);
            ldsm4(ql[kt], qa + 8 * 2304);
        }

        float O[8][4];
        #pragma unroll
        for (int nv = 0; nv < 8; nv++)
            #pragma unroll
            for (int e = 0; e < 4; e++) O[nv][e] = 0.f;
        float m0 = -1e30f, m1 = -1e30f, l0 = 0.f, l1 = 0.f;

        for (int t = 0; t < NKT; t++) {
            const int j0 = t * 64;
            float S[8][4];
            #pragma unroll
            for (int nt = 0; nt < 8; nt++)
                #pragma unroll
                for (int e = 0; e < 4; e++) S[nt][e] = 0.f;

            #pragma unroll
            for (int c = 0; c < 4; c++) {
                #pragma unroll
                for (int nt = 0; nt < 8; nt++) {
                    uint32_t ka = sb + kvb + (j0 + nt * 8 + (lane & 7)) * 144
                                + c * 32 + ((lane >> 3) & 1) * 16;
                    uint32_t kh2[2], kl2[2];
                    ldsm2(kh2, ka);
                    ldsm2(kl2, ka + MATB);
                    mma_bf16(S[nt], qh[c], kh2);
                    mma_bf16(S[nt], qh[c], kl2);
                    mma_bf16(S[nt], ql[c], kh2);
                }
            }

            float mx0 = S[0][0], mx1 = S[0][2];
            #pragma unroll
            for (int nt = 0; nt < 8; nt++) {
                mx0 = fmaxf(mx0, fmaxf(S[nt][0], S[nt][1]));
                mx1 = fmaxf(mx1, fmaxf(S[nt][2], S[nt][3]));
            }
            mx0 = fmaxf(mx0, __shfl_xor_sync(0xffffffffu, mx0, 1));
            mx0 = fmaxf(mx0, __shfl_xor_sync(0xffffffffu, mx0, 2));
            mx1 = fmaxf(mx1, __shfl_xor_sync(0xffffffffu, mx1, 1));
            mx1 = fmaxf(mx1, __shfl_xor_sync(0xffffffffu, mx1, 2));
            float mn0 = fmaxf(m0, mx0), mn1 = fmaxf(m1, mx1);
            float sc0 = __expf(m0 - mn0), sc1 = __expf(m1 - mn1);
            m0 = mn0; m1 = mn1;

            float sum0 = 0.f, sum1 = 0.f;
            #pragma unroll
            for (int nt = 0; nt < 8; nt++) {
                S[nt][0] = __expf(S[nt][0] - m0);
                S[nt][1] = __expf(S[nt][1] - m0);
                S[nt][2] = __expf(S[nt][2] - m1);
                S[nt][3] = __expf(S[nt][3] - m1);
                sum0 += S[nt][0] + S[nt][1];
                sum1 += S[nt][2] + S[nt][3];
            }
            sum0 += __shfl_xor_sync(0xffffffffu, sum0, 1);
            sum0 += __shfl_xor_sync(0xffffffffu, sum0, 2);
            sum1 += __shfl_xor_sync(0xffffffffu, sum1, 1);
            sum1 += __shfl_xor_sync(0xffffffffu, sum1, 2);
            l0 = l0 * sc0 + sum0;
            l1 = l1 * sc1 + sum1;
            #pragma unroll
            for (int nv = 0; nv < 8; nv++) {
                O[nv][0] *= sc0; O[nv][1] *= sc0;
                O[nv][2] *= sc1; O[nv][3] *= sc1;
            }

            #pragma unroll
            for (int kp = 0; kp < 4; kp++) {
                uint32_t aph[4], apl[4];
                #pragma unroll
                for (int half = 0; half < 2; half++) {
                    const float* Sv = S[2 * kp + half];
                    uint32_t w0 = packbf(Sv[0], Sv[1]);
                    uint32_t w1 = packbf(Sv[2], Sv[3]);
                    float2 h0 = bfhi2f(w0), h1 = bfhi2f(w1);
                    aph[2 * half]     = w0;
                    aph[2 * half + 1] = w1;
                    apl[2 * half]     = packbf(Sv[0] - h0.x, Sv[1] - h0.y);
                    apl[2 * half + 1] = packbf(Sv[2] - h1.x, Sv[3] - h1.y);
                }
                uint32_t vrow = (uint32_t)(j0 + kp * 16 + ((lane >> 3) & 1) * 8 + (lane & 7));
                #pragma unroll
                for (int nv = 0; nv < 8; nv++) {
                    uint32_t va = sb + kvb + 2 * MATB + vrow * 144 + nv * 16;
                    uint32_t vh2[2], vl2[2];
                    ldsm2t(vh2, va);
                    ldsm2t(vl2, va + MATB);
                    mma_bf16(O[nv], aph, vh2);
                    mma_bf16(O[nv], aph, vl2);
                    mma_bf16(O[nv], apl, vh2);
                }
            }
        }

        float inv0 = 1.f / l0, inv1 = 1.f / l1;
        int r = qrow0 + (lane >> 2);
        long t0 = ISROW ? (tok0 + r) : ((long)(b * 64 + r) * 256 + lcoord);
        long t1 = ISROW ? (tok0 + r + 8) : ((long)(b * 64 + r + 8) * 256 + lcoord);
        #pragma unroll
        for (int nv = 0; nv < 8; nv++) {
            int col = h * 64 + nv * 8 + (lane & 3) * 2;
            float2 o0, o1;
            o0.x = O[nv][0] * inv0; o0.y = O[nv][1] * inv0;
            o1.x = O[nv][2] * inv1; o1.y = O[nv][3] * inv1;
            *(float2*)&out[t0 * 512 + col] = o0;
            *(float2*)&out[t1 * 512 + col] = o1;
        }
        __syncwarp();
    }
}

// ---------------------------------------------------------------------------
// out = LayerNorm(a + b) * g + beta; optionally also emit bf16 hi/lo split.
// ---------------------------------------------------------------------------
template<bool SPLIT>
__global__ void add_ln(const float* __restrict__ a, const float* __restrict__ b,
                       const float* __restrict__ g, const float* __restrict__ be,
                       float* __restrict__ out,
                       __nv_bfloat16* __restrict__ hi, __nv_bfloat16* __restrict__ lo) {
    int row = blockIdx.x * 8 + (threadIdx.x >> 5);
    int lane = threadIdx.x & 31;
    const float* pa = a + (size_t)row * 512;
    const float* pb = b + (size_t)row * 512;
    float v[16];
    float sum = 0.f;
    #pragma unroll
    for (int i = 0; i < 4; i++) {
        int c = lane * 4 + i * 128;
        float4 x = *(const float4*)&pa[c];
        float4 y = *(const float4*)&pb[c];
        v[i*4+0] = x.x + y.x; v[i*4+1] = x.y + y.y;
        v[i*4+2] = x.z + y.z; v[i*4+3] = x.w + y.w;
        sum += v[i*4+0] + v[i*4+1] + v[i*4+2] + v[i*4+3];
    }
    #pragma unroll
    for (int o = 16; o > 0; o >>= 1) sum += __shfl_xor_sync(0xffffffffu, sum, o);
    float mu = sum * (1.f / 512.f);
    float var = 0.f;
    #pragma unroll
    for (int i = 0; i < 16; i++) { float d = v[i] - mu; var += d * d; }
    #pragma unroll
    for (int o = 16; o > 0; o >>= 1) var += __shfl_xor_sync(0xffffffffu, var, o);
    float rstd = rsqrtf(var * (1.f / 512.f) + 1e-5f);
    float* po = out + (size_t)row * 512;
    #pragma unroll
    for (int i = 0; i < 4; i++) {
        int c = lane * 4 + i * 128;
        float4 gg = *(const float4*)&g[c];
        float4 bb = *(const float4*)&be[c];
        float4 o4;
        o4.x = (v[i*4+0] - mu) * rstd * gg.x + bb.x;
        o4.y = (v[i*4+1] - mu) * rstd * gg.y + bb.y;
        o4.z = (v[i*4+2] - mu) * rstd * gg.z + bb.z;
        o4.w = (v[i*4+3] - mu) * rstd * gg.w + bb.w;
        *(float4*)&po[c] = o4;
        if (SPLIT) {
            uint32_t h0 = packbf(o4.x, o4.y), h1 = packbf(o4.z, o4.w);
            float2 f0 = bfhi2f(h0), f1 = bfhi2f(h1);
            size_t w = (size_t)row * 256 + c / 2;
            ((uint32_t*)hi)[w]     = h0;
            ((uint32_t*)hi)[w + 1] = h1;
            ((uint32_t*)lo)[w]     = packbf(o4.x - f0.x, o4.y - f0.y);
            ((uint32_t*)lo)[w + 1] = packbf(o4.z - f1.x, o4.w - f1.y);
        }
    }
}

// ---------------------------------------------------------------------------

extern "C" void kernel_launch(void* const* d_in, const int* in_sizes, int n_in,
                              void* d_out, int out_size) {
    const float* x     = (const float*)d_in[0];
    const float* w_row = (const float*)d_in[1];
    const float* b_row = (const float*)d_in[2];
    const float* w_col = (const float*)d_in[3];
    const float* b_col = (const float*)d_in[4];
    const float* g1    = (const float*)d_in[5];
    const float* be1   = (const float*)d_in[6];
    const float* g2    = (const float*)d_in[7];
    const float* be2   = (const float*)d_in[8];
    float* out = (float*)d_out;

    float *qkv, *attn, *out1;
    __nv_bfloat16 *ahi, *alo, *whi, *wlo;
    cudaGetSymbolAddress((void**)&qkv,  g_qkv);
    cudaGetSymbolAddress((void**)&attn, g_attn);
    cudaGetSymbolAddress((void**)&out1, g_out1);
    cudaGetSymbolAddress((void**)&ahi,  g_ahi);
    cudaGetSymbolAddress((void**)&alo,  g_alo);
    cudaGetSymbolAddress((void**)&whi,  g_whi);
    cudaGetSymbolAddress((void**)&wlo,  g_wlo);

    const int smem_row = 4 * 256 * 144 + 2 * 8 * 16 * 144;   // 184320
    const int smem_col = 8 * 64 * 144 + 2 * 8 * 16 * 144;    // 110592
    cudaFuncSetAttribute(attn_mma<true>,
                         cudaFuncAttributeMaxDynamicSharedMemorySize, smem_row);
    cudaFuncSetAttribute(attn_mma<false>,
                         cudaFuncAttributeMaxDynamicSharedMemorySize, smem_col);
    cudaFuncSetAttribute(gemm_mma,
                         cudaFuncAttributeMaxDynamicSharedMemorySize, GEMM_SMEM);

    const int n4x = M_TOK * KD / 4;
    const int n4w = N3D * KD / 4;
    dim3 ggrid(N3D / 256, M_TOK / 128);   // (6, 256)

    split_bf16<<<(n4x + 255) / 256, 256>>>(x, ahi, alo, n4x);
    split_bf16<<<(n4w + 255) / 256, 256>>>(w_row, whi, wlo, n4w);
    gemm_mma<<<ggrid, 256, GEMM_SMEM>>>(ahi, alo, whi, wlo, b_row, qkv);
    attn_mma<true><<<1024, 256, smem_row>>>(qkv, attn);
    add_ln<true><<<M_TOK / 8, 256>>>(x, attn, g1, be1, out1, ahi, alo);

    split_bf16<<<(n4w + 255) / 256, 256>>>(w_col, whi, wlo, n4w);
    gemm_mma<<<ggrid, 256, GEMM_SMEM>>>(ahi, alo, whi, wlo, b_col, qkv);
    attn_mma<false><<<2048, 256, smem_col>>>(qkv, attn);
    add_ln<false><<<M_TOK / 8, 256>>>(out1, attn, g2, be2, out, nullptr, nullptr);
}

// round 7
// speedup vs baseline: 3.1919x; 1.1968x over previous
#include <cuda_runtime.h>
#include <cuda_bf16.h>
#include <math.h>
#include <cstdint>

// AxialSelfAttention2d: B=2,S=64,L=256,H=8,C=64,D=512
// Projections + attention on legacy mma.sync bf16 hi/lo split tensor cores.
// GEMM: CTA 128x128, 4 warps (64x64), XOR-swizzled 64B smem rows,
// 3-stage cp.async pipeline, 2 CTAs/SM.

#define M_TOK 32768
#define N3D 1536
#define KD 512

__device__ float g_qkv[(size_t)M_TOK * N3D];
__device__ float g_attn[(size_t)M_TOK * 512];
__device__ float g_out1[(size_t)M_TOK * 512];
__device__ __nv_bfloat16 g_ahi[(size_t)M_TOK * KD];
__device__ __nv_bfloat16 g_alo[(size_t)M_TOK * KD];
__device__ __nv_bfloat16 g_whi[(size_t)N3D * KD];
__device__ __nv_bfloat16 g_wlo[(size_t)N3D * KD];

// ---------------------------------------------------------------------------
// helpers
// ---------------------------------------------------------------------------
__device__ __forceinline__ uint32_t smem_u32(const void* p) {
    uint32_t a;
    asm("{ .reg .u64 t; cvta.to.shared.u64 t, %1; cvt.u32.u64 %0, t; }" : "=r"(a) : "l"(p));
    return a;
}
__device__ __forceinline__ void ldsm4(uint32_t* r, uint32_t a) {
    asm volatile("ldmatrix.sync.aligned.m8n8.x4.shared.b16 {%0,%1,%2,%3}, [%4];"
        : "=r"(r[0]), "=r"(r[1]), "=r"(r[2]), "=r"(r[3]) : "r"(a));
}
__device__ __forceinline__ void ldsm2(uint32_t* r, uint32_t a) {
    asm volatile("ldmatrix.sync.aligned.m8n8.x2.shared.b16 {%0,%1}, [%2];"
        : "=r"(r[0]), "=r"(r[1]) : "r"(a));
}
__device__ __forceinline__ void ldsm2t(uint32_t* r, uint32_t a) {
    asm volatile("ldmatrix.sync.aligned.m8n8.x2.trans.shared.b16 {%0,%1}, [%2];"
        : "=r"(r[0]), "=r"(r[1]) : "r"(a));
}
__device__ __forceinline__ void mma_bf16(float* c, const uint32_t* a, const uint32_t* b) {
    asm volatile("mma.sync.aligned.m16n8k16.row.col.f32.bf16.bf16.f32 "
        "{%0,%1,%2,%3}, {%4,%5,%6,%7}, {%8,%9}, {%0,%1,%2,%3};"
        : "+f"(c[0]), "+f"(c[1]), "+f"(c[2]), "+f"(c[3])
        : "r"(a[0]), "r"(a[1]), "r"(a[2]), "r"(a[3]), "r"(b[0]), "r"(b[1]));
}
__device__ __forceinline__ uint32_t packbf(float lo, float hi) {
    uint32_t r;
    asm("cvt.rn.bf16x2.f32 %0, %1, %2;" : "=r"(r) : "f"(hi), "f"(lo));
    return r;
}
__device__ __forceinline__ float2 bfhi2f(uint32_t w) {
    float2 r;
    r.x = __uint_as_float(w << 16);
    r.y = __uint_as_float(w & 0xffff0000u);
    return r;
}
__device__ __forceinline__ void cpasync16(uint32_t dst, const void* src) {
    asm volatile("cp.async.cg.shared.global [%0], [%1], 16;" :: "r"(dst), "l"(src));
}
#define CP_COMMIT() asm volatile("cp.async.commit_group;" ::: "memory")
#define CP_WAIT1()  asm volatile("cp.async.wait_group 1;" ::: "memory")

// ---------------------------------------------------------------------------
// hi/lo bf16 split: hi = bf16(a), lo = bf16(a - float(hi))
// ---------------------------------------------------------------------------
__global__ void split_bf16(const float* __restrict__ in, __nv_bfloat16* __restrict__ hi,
                           __nv_bfloat16* __restrict__ lo, int n4) {
    int i = blockIdx.x * 256 + threadIdx.x;
    if (i >= n4) return;
    float4 v = ((const float4*)in)[i];
    uint32_t h0 = packbf(v.x, v.y), h1 = packbf(v.z, v.w);
    float2 f0 = bfhi2f(h0), f1 = bfhi2f(h1);
    ((uint32_t*)hi)[2*i]   = h0;
    ((uint32_t*)hi)[2*i+1] = h1;
    ((uint32_t*)lo)[2*i]   = packbf(v.x - f0.x, v.y - f0.y);
    ((uint32_t*)lo)[2*i+1] = packbf(v.z - f1.x, v.w - f1.y);
}

// ---------------------------------------------------------------------------
// GEMM via mma.sync: C[M,1536] = (Ahi+Alo)(Whi+Wlo)^T + bias (3 products)
// CTA 128x128, 4 warps (2m x 2n), warp tile 64x64.
// Smem: exact 64B rows with XOR swizzle (col16 ^= (row>>1)&3) -> conflict-free
// ldmatrix, stage = 32KB, 3 stages = 96KB -> 2 CTAs/SM.
// ---------------------------------------------------------------------------
#define STG2   32768
#define RG_AHI 0
#define RG_ALO 8192
#define RG_WHI 16384
#define RG_WLO 24576
#define GEMM_SMEM (3 * STG2)   // 98304

__global__ __launch_bounds__(128, 2)
void gemm_mma(const __nv_bfloat16* __restrict__ ahi, const __nv_bfloat16* __restrict__ alo,
              const __nv_bfloat16* __restrict__ whi, const __nv_bfloat16* __restrict__ wlo,
              const float* __restrict__ bias, float* __restrict__ C) {
    extern __shared__ char smg[];
    const uint32_t sb = smem_u32(smg);
    const int tid = threadIdx.x;
    const int lane = tid & 31, warp = tid >> 5;
    const int wm = (warp >> 1) * 64;
    const int wn = (warp & 1) * 64;
    const int m0 = blockIdx.y * 128;
    const int n0 = blockIdx.x * 128;

    // loader: 2048 16B vecs/stage, 16 per thread (4 regions x 4 row-groups)
    const __nv_bfloat16* bases[4];
    bases[0] = ahi + (size_t)m0 * KD;
    bases[1] = alo + (size_t)m0 * KD;
    bases[2] = whi + (size_t)n0 * KD;
    bases[3] = wlo + (size_t)n0 * KD;
    const int lrow = tid >> 2;          // 0..31
    const int lv = tid & 3;             // 16B col
    const uint32_t dbase = (uint32_t)(lrow * 64 + ((lv ^ ((lrow >> 1) & 3)) << 4));
    const size_t goff = (size_t)lrow * KD + lv * 8;

    #define GEMM_ISSUE(kc) do { \
        uint32_t _s = sb + ((kc) % 3) * STG2 + dbase; \
        _Pragma("unroll") \
        for (int rg = 0; rg < 4; rg++) { \
            const __nv_bfloat16* _b = bases[rg] + goff + (kc) * 32; \
            _Pragma("unroll") \
            for (int j = 0; j < 4; j++) \
                cpasync16(_s + rg * 8192 + j * 2048, _b + (size_t)j * 32 * KD); \
        } \
        CP_COMMIT(); \
    } while (0)

    GEMM_ISSUE(0);
    GEMM_ISSUE(1);

    float acc[4][8][4];
    #pragma unroll
    for (int mt = 0; mt < 4; mt++)
        #pragma unroll
        for (int nt = 0; nt < 8; nt++)
            #pragma unroll
            for (int e = 0; e < 4; e++) acc[mt][nt][e] = 0.f;

    // fragment lane addressing (row within 16-row block, 16B col selector)
    const uint32_t fr = lane & 15;
    const uint32_t fahi = lane >> 4;                              // A: col16 bit
    const uint32_t fbr = (lane & 7) + ((lane >> 4) << 3);         // B row
    const uint32_t fbhi = (lane >> 3) & 1;                        // B: col16 bit

    for (int kc = 0; kc < KD / 32; kc++) {
        CP_WAIT1();
        __syncthreads();
        if (kc + 2 < KD / 32) GEMM_ISSUE(kc + 2);

        const uint32_t st = sb + (kc % 3) * STG2;
        #pragma unroll
        for (int ks = 0; ks < 2; ks++) {
            uint32_t ah[4][4], bh[4][4];
            #pragma unroll
            for (int mt = 0; mt < 4; mt++) {
                uint32_t R = wm + mt * 16 + fr;
                uint32_t c16 = (ks * 2 + fahi) ^ ((R >> 1) & 3);
                ldsm4(ah[mt], st + RG_AHI + R * 64 + c16 * 16);
            }
            #pragma unroll
            for (int np = 0; np < 4; np++) {
                uint32_t R = wn + np * 16 + fbr;
                uint32_t c16 = (ks * 2 + fbhi) ^ ((R >> 1) & 3);
                ldsm4(bh[np], st + RG_WHI + R * 64 + c16 * 16);
            }
            #pragma unroll
            for (int mt = 0; mt < 4; mt++)
                #pragma unroll
                for (int nt = 0; nt < 8; nt++)
                    mma_bf16(acc[mt][nt], ah[mt], &bh[nt >> 1][(nt & 1) * 2]);

            uint32_t bl[4][4];
            #pragma unroll
            for (int np = 0; np < 4; np++) {
                uint32_t R = wn + np * 16 + fbr;
                uint32_t c16 = (ks * 2 + fbhi) ^ ((R >> 1) & 3);
                ldsm4(bl[np], st + RG_WLO + R * 64 + c16 * 16);
            }
            #pragma unroll
            for (int mt = 0; mt < 4; mt++)
                #pragma unroll
                for (int nt = 0; nt < 8; nt++)
                    mma_bf16(acc[mt][nt], ah[mt], &bl[nt >> 1][(nt & 1) * 2]);

            uint32_t al[4][4];
            #pragma unroll
            for (int mt = 0; mt < 4; mt++) {
                uint32_t R = wm + mt * 16 + fr;
                uint32_t c16 = (ks * 2 + fahi) ^ ((R >> 1) & 3);
                ldsm4(al[mt], st + RG_ALO + R * 64 + c16 * 16);
            }
            #pragma unroll
            for (int mt = 0; mt < 4; mt++)
                #pragma unroll
                for (int nt = 0; nt < 8; nt++)
                    mma_bf16(acc[mt][nt], al[mt], &bh[nt >> 1][(nt & 1) * 2]);
        }
    }

    #pragma unroll
    for (int mt = 0; mt < 4; mt++) {
        int row0 = m0 + wm + mt * 16 + (lane >> 2);
        #pragma unroll
        for (int nt = 0; nt < 8; nt++) {
            int col = n0 + wn + nt * 8 + (lane & 3) * 2;
            float2 bv = *(const float2*)&bias[col];
            float2 o0, o1;
            o0.x = acc[mt][nt][0] + bv.x; o0.y = acc[mt][nt][1] + bv.y;
            o1.x = acc[mt][nt][2] + bv.x; o1.y = acc[mt][nt][3] + bv.y;
            *(float2*)&C[(size_t)row0 * N3D + col] = o0;
            *(float2*)&C[(size_t)(row0 + 8) * N3D + col] = o1;
        }
    }
}

// ---------------------------------------------------------------------------
// Flash attention via mma.sync, bf16 hi/lo split (unchanged from R5/R6).
// ---------------------------------------------------------------------------
template<bool ISROW>
__global__ __launch_bounds__(256, 1)
void attn_mma(const float* __restrict__ qkv, float* __restrict__ out) {
    constexpr int NK   = ISROW ? 256 : 64;
    constexpr int NKT  = NK / 64;
    constexpr int NPASS = ISROW ? 2 : 1;
    constexpr int MATB = NK * 144;
    extern __shared__ char sm[];
    const uint32_t sb = smem_u32(sm);
    const int tid = threadIdx.x, lane = tid & 31, warp = tid >> 5;
    const int bid = blockIdx.x;

    int b, h;
    long tok0 = 0;
    int lcoord = 0;
    uint32_t kvb;
    uint32_t QHIo;

    if (ISROW) {
        h = bid & 7;
        int s = (bid >> 3) & 63;
        b = bid >> 9;
        tok0 = (long)(b * 64 + s) * 256;
        kvb = 0;
        QHIo = 4 * MATB;
    } else {
        int hp = bid & 3;
        lcoord = (bid >> 2) & 255;
        b = bid >> 10;
        int lh = warp >> 2;
        h = hp * 2 + lh;
        kvb = (uint32_t)lh * 4 * MATB;
        QHIo = 8 * MATB;
    }

    if (ISROW) {
        for (int idx = tid; idx < NK * 32; idx += 256) {
            int j = idx >> 5, c2 = idx & 31;
            long g = (tok0 + j) * 1536 + h * 64 + c2 * 2;
            float2 kf = *(const float2*)&qkv[g + 512];
            float2 vf = *(const float2*)&qkv[g + 1024];
            uint32_t kw = packbf(kf.x, kf.y);
            uint32_t vw = packbf(vf.x, vf.y);
            float2 kh = bfhi2f(kw), vh = bfhi2f(vw);
            uint32_t off = j * 144 + c2 * 4;
            *(uint32_t*)(sm + off)            = kw;
            *(uint32_t*)(sm + MATB + off)     = packbf(kf.x - kh.x, kf.y - kh.y);
            *(uint32_t*)(sm + 2 * MATB + off) = vw;
            *(uint32_t*)(sm + 3 * MATB + off) = packbf(vf.x - vh.x, vf.y - vh.y);
        }
    } else {
        int hp = bid & 3;
        for (int idx = tid; idx < 2 * 64 * 32; idx += 256) {
            int lh = idx >> 11, j = (idx >> 5) & 63, c2 = idx & 31;
            long g = ((long)(b * 64 + j) * 256 + lcoord) * 1536 + (hp * 2 + lh) * 64 + c2 * 2;
            float2 kf = *(const float2*)&qkv[g + 512];
            float2 vf = *(const float2*)&qkv[g + 1024];
            uint32_t kw = packbf(kf.x, kf.y);
            uint32_t vw = packbf(vf.x, vf.y);
            float2 kh = bfhi2f(kw), vh = bfhi2f(vw);
            uint32_t base = (uint32_t)lh * 4 * MATB;
            uint32_t off = j * 144 + c2 * 4;
            *(uint32_t*)(sm + base + off)            = kw;
            *(uint32_t*)(sm + base + MATB + off)     = packbf(kf.x - kh.x, kf.y - kh.y);
            *(uint32_t*)(sm + base + 2 * MATB + off) = vw;
            *(uint32_t*)(sm + base + 3 * MATB + off) = packbf(vf.x - vh.x, vf.y - vh.y);
        }
    }
    __syncthreads();

    const uint32_t qwb = QHIo + warp * 2304;

    for (int p = 0; p < NPASS; p++) {
        const int qrow0 = ISROW ? (p * 8 + warp) * 16 : (warp & 3) * 16;

        for (int f = lane; f < 256; f += 32) {
            int row = f >> 4, c4 = f & 15;
            long ti = ISROW ? (tok0 + qrow0 + row)
                            : ((long)(b * 64 + qrow0 + row) * 256 + lcoord);
            float4 qv = *(const float4*)&qkv[ti * 1536 + h * 64 + c4 * 4];
            uint32_t w0 = packbf(qv.x, qv.y), w1 = packbf(qv.z, qv.w);
            float2 f0 = bfhi2f(w0), f1 = bfhi2f(w1);
            uint32_t* d = (uint32_t*)(sm + qwb + row * 144 + c4 * 8);
            d[0] = w0; d[1] = w1;
            uint32_t* dl = (uint32_t*)(sm + qwb + 8 * 2304 + row * 144 + c4 * 8);
            dl[0] = packbf(qv.x - f0.x, qv.y - f0.y);
            dl[1] = packbf(qv.z - f1.x, qv.w - f1.y);
        }
        __syncwarp();

        uint32_t qh[4][4], ql[4][4];
        #pragma unroll
        for (int kt = 0; kt < 4; kt++) {
            uint32_t qa = sb + qwb + (lane & 15) * 144 + kt * 32 + (lane >> 4) * 16;
            ldsm4(qh[kt], qa);
            ldsm4(ql[kt], qa + 8 * 2304);
        }

        float O[8][4];
        #pragma unroll
        for (int nv = 0; nv < 8; nv++)
            #pragma unroll
            for (int e = 0; e < 4; e++) O[nv][e] = 0.f;
        float m0 = -1e30f, m1 = -1e30f, l0 = 0.f, l1 = 0.f;

        for (int t = 0; t < NKT; t++) {
            const int j0 = t * 64;
            float S[8][4];
            #pragma unroll
            for (int nt = 0; nt < 8; nt++)
                #pragma unroll
                for (int e = 0; e < 4; e++) S[nt][e] = 0.f;

            #pragma unroll
            for (int c = 0; c < 4; c++) {
                #pragma unroll
                for (int nt = 0; nt < 8; nt++) {
                    uint32_t ka = sb + kvb + (j0 + nt * 8 + (lane & 7)) * 144
                                + c * 32 + ((lane >> 3) & 1) * 16;
                    uint32_t kh2[2], kl2[2];
                    ldsm2(kh2, ka);
                    ldsm2(kl2, ka + MATB);
                    mma_bf16(S[nt], qh[c], kh2);
                    mma_bf16(S[nt], qh[c], kl2);
                    mma_bf16(S[nt], ql[c], kh2);
                }
            }

            float mx0 = S[0][0], mx1 = S[0][2];
            #pragma unroll
            for (int nt = 0; nt < 8; nt++) {
                mx0 = fmaxf(mx0, fmaxf(S[nt][0], S[nt][1]));
                mx1 = fmaxf(mx1, fmaxf(S[nt][2], S[nt][3]));
            }
            mx0 = fmaxf(mx0, __shfl_xor_sync(0xffffffffu, mx0, 1));
            mx0 = fmaxf(mx0, __shfl_xor_sync(0xffffffffu, mx0, 2));
            mx1 = fmaxf(mx1, __shfl_xor_sync(0xffffffffu, mx1, 1));
            mx1 = fmaxf(mx1, __shfl_xor_sync(0xffffffffu, mx1, 2));
            float mn0 = fmaxf(m0, mx0), mn1 = fmaxf(m1, mx1);
            float sc0 = __expf(m0 - mn0), sc1 = __expf(m1 - mn1);
            m0 = mn0; m1 = mn1;

            float sum0 = 0.f, sum1 = 0.f;
            #pragma unroll
            for (int nt = 0; nt < 8; nt++) {
                S[nt][0] = __expf(S[nt][0] - m0);
                S[nt][1] = __expf(S[nt][1] - m0);
                S[nt][2] = __expf(S[nt][2] - m1);
                S[nt][3] = __expf(S[nt][3] - m1);
                sum0 += S[nt][0] + S[nt][1];
                sum1 += S[nt][2] + S[nt][3];
            }
            sum0 += __shfl_xor_sync(0xffffffffu, sum0, 1);
            sum0 += __shfl_xor_sync(0xffffffffu, sum0, 2);
            sum1 += __shfl_xor_sync(0xffffffffu, sum1, 1);
            sum1 += __shfl_xor_sync(0xffffffffu, sum1, 2);
            l0 = l0 * sc0 + sum0;
            l1 = l1 * sc1 + sum1;
            #pragma unroll
            for (int nv = 0; nv < 8; nv++) {
                O[nv][0] *= sc0; O[nv][1] *= sc0;
                O[nv][2] *= sc1; O[nv][3] *= sc1;
            }

            #pragma unroll
            for (int kp = 0; kp < 4; kp++) {
                uint32_t aph[4], apl[4];
                #pragma unroll
                for (int half = 0; half < 2; half++) {
                    const float* Sv = S[2 * kp + half];
                    uint32_t w0 = packbf(Sv[0], Sv[1]);
                    uint32_t w1 = packbf(Sv[2], Sv[3]);
                    float2 h0 = bfhi2f(w0), h1 = bfhi2f(w1);
                    aph[2 * half]     = w0;
                    aph[2 * half + 1] = w1;
                    apl[2 * half]     = packbf(Sv[0] - h0.x, Sv[1] - h0.y);
                    apl[2 * half + 1] = packbf(Sv[2] - h1.x, Sv[3] - h1.y);
                }
                uint32_t vrow = (uint32_t)(j0 + kp * 16 + ((lane >> 3) & 1) * 8 + (lane & 7));
                #pragma unroll
                for (int nv = 0; nv < 8; nv++) {
                    uint32_t va = sb + kvb + 2 * MATB + vrow * 144 + nv * 16;
                    uint32_t vh2[2], vl2[2];
                    ldsm2t(vh2, va);
                    ldsm2t(vl2, va + MATB);
                    mma_bf16(O[nv], aph, vh2);
                    mma_bf16(O[nv], aph, vl2);
                    mma_bf16(O[nv], apl, vh2);
                }
            }
        }

        float inv0 = 1.f / l0, inv1 = 1.f / l1;
        int r = qrow0 + (lane >> 2);
        long t0 = ISROW ? (tok0 + r) : ((long)(b * 64 + r) * 256 + lcoord);
        long t1 = ISROW ? (tok0 + r + 8) : ((long)(b * 64 + r + 8) * 256 + lcoord);
        #pragma unroll
        for (int nv = 0; nv < 8; nv++) {
            int col = h * 64 + nv * 8 + (lane & 3) * 2;
            float2 o0, o1;
            o0.x = O[nv][0] * inv0; o0.y = O[nv][1] * inv0;
            o1.x = O[nv][2] * inv1; o1.y = O[nv][3] * inv1;
            *(float2*)&out[t0 * 512 + col] = o0;
            *(float2*)&out[t1 * 512 + col] = o1;
        }
        __syncwarp();
    }
}

// ---------------------------------------------------------------------------
// out = LayerNorm(a + b) * g + beta; optionally also emit bf16 hi/lo split.
// ---------------------------------------------------------------------------
template<bool SPLIT>
__global__ void add_ln(const float* __restrict__ a, const float* __restrict__ b,
                       const float* __restrict__ g, const float* __restrict__ be,
                       float* __restrict__ out,
                       __nv_bfloat16* __restrict__ hi, __nv_bfloat16* __restrict__ lo) {
    int row = blockIdx.x * 8 + (threadIdx.x >> 5);
    int lane = threadIdx.x & 31;
    const float* pa = a + (size_t)row * 512;
    const float* pb = b + (size_t)row * 512;
    float v[16];
    float sum = 0.f;
    #pragma unroll
    for (int i = 0; i < 4; i++) {
        int c = lane * 4 + i * 128;
        float4 x = *(const float4*)&pa[c];
        float4 y = *(const float4*)&pb[c];
        v[i*4+0] = x.x + y.x; v[i*4+1] = x.y + y.y;
        v[i*4+2] = x.z + y.z; v[i*4+3] = x.w + y.w;
        sum += v[i*4+0] + v[i*4+1] + v[i*4+2] + v[i*4+3];
    }
    #pragma unroll
    for (int o = 16; o > 0; o >>= 1) sum += __shfl_xor_sync(0xffffffffu, sum, o);
    float mu = sum * (1.f / 512.f);
    float var = 0.f;
    #pragma unroll
    for (int i = 0; i < 16; i++) { float d = v[i] - mu; var += d * d; }
    #pragma unroll
    for (int o = 16; o > 0; o >>= 1) var += __shfl_xor_sync(0xffffffffu, var, o);
    float rstd = rsqrtf(var * (1.f / 512.f) + 1e-5f);
    float* po = out + (size_t)row * 512;
    #pragma unroll
    for (int i = 0; i < 4; i++) {
        int c = lane * 4 + i * 128;
        float4 gg = *(const float4*)&g[c];
        float4 bb = *(const float4*)&be[c];
        float4 o4;
        o4.x = (v[i*4+0] - mu) * rstd * gg.x + bb.x;
        o4.y = (v[i*4+1] - mu) * rstd * gg.y + bb.y;
        o4.z = (v[i*4+2] - mu) * rstd * gg.z + bb.z;
        o4.w = (v[i*4+3] - mu) * rstd * gg.w + bb.w;
        *(float4*)&po[c] = o4;
        if (SPLIT) {
            uint32_t h0 = packbf(o4.x, o4.y), h1 = packbf(o4.z, o4.w);
            float2 f0 = bfhi2f(h0), f1 = bfhi2f(h1);
            size_t w = (size_t)row * 256 + c / 2;
            ((uint32_t*)hi)[w]     = h0;
            ((uint32_t*)hi)[w + 1] = h1;
            ((uint32_t*)lo)[w]     = packbf(o4.x - f0.x, o4.y - f0.y);
            ((uint32_t*)lo)[w + 1] = packbf(o4.z - f1.x, o4.w - f1.y);
        }
    }
}

// ---------------------------------------------------------------------------

extern "C" void kernel_launch(void* const* d_in, const int* in_sizes, int n_in,
                              void* d_out, int out_size) {
    const float* x     = (const float*)d_in[0];
    const float* w_row = (const float*)d_in[1];
    const float* b_row = (const float*)d_in[2];
    const float* w_col = (const float*)d_in[3];
    const float* b_col = (const float*)d_in[4];
    const float* g1    = (const float*)d_in[5];
    const float* be1   = (const float*)d_in[6];
    const float* g2    = (const float*)d_in[7];
    const float* be2   = (const float*)d_in[8];
    float* out = (float*)d_out;

    float *qkv, *attn, *out1;
    __nv_bfloat16 *ahi, *alo, *whi, *wlo;
    cudaGetSymbolAddress((void**)&qkv,  g_qkv);
    cudaGetSymbolAddress((void**)&attn, g_attn);
    cudaGetSymbolAddress((void**)&out1, g_out1);
    cudaGetSymbolAddress((void**)&ahi,  g_ahi);
    cudaGetSymbolAddress((void**)&alo,  g_alo);
    cudaGetSymbolAddress((void**)&whi,  g_whi);
    cudaGetSymbolAddress((void**)&wlo,  g_wlo);

    const int smem_row = 4 * 256 * 144 + 2 * 8 * 16 * 144;   // 184320
    const int smem_col = 8 * 64 * 144 + 2 * 8 * 16 * 144;    // 110592
    cudaFuncSetAttribute(attn_mma<true>,
                         cudaFuncAttributeMaxDynamicSharedMemorySize, smem_row);
    cudaFuncSetAttribute(attn_mma<false>,
                         cudaFuncAttributeMaxDynamicSharedMemorySize, smem_col);
    cudaFuncSetAttribute(gemm_mma,
                         cudaFuncAttributeMaxDynamicSharedMemorySize, GEMM_SMEM);

    const int n4x = M_TOK * KD / 4;
    const int n4w = N3D * KD / 4;
    dim3 ggrid(N3D / 128, M_TOK / 128);   // (12, 256)

    split_bf16<<<(n4x + 255) / 256, 256>>>(x, ahi, alo, n4x);
    split_bf16<<<(n4w + 255) / 256, 256>>>(w_row, whi, wlo, n4w);
    gemm_mma<<<ggrid, 128, GEMM_SMEM>>>(ahi, alo, whi, wlo, b_row, qkv);
    attn_mma<true><<<1024, 256, smem_row>>>(qkv, attn);
    add_ln<true><<<M_TOK / 8, 256>>>(x, attn, g1, be1, out1, ahi, alo);

    split_bf16<<<(n4w + 255) / 256, 256>>>(w_col, whi, wlo, n4w);
    gemm_mma<<<ggrid, 128, GEMM_SMEM>>>(ahi, alo, whi, wlo, b_col, qkv);
    attn_mma<false><<<2048, 256, smem_col>>>(qkv, attn);
    add_ln<false><<<M_TOK / 8, 256>>>(out1, attn, g2, be2, out, nullptr, nullptr);
}

// round 8
// speedup vs baseline: 3.2651x; 1.0229x over previous
#include <cuda_runtime.h>
#include <cuda_bf16.h>
#include <math.h>
#include <cstdint>

// AxialSelfAttention2d: B=2,S=64,L=256,H=8,C=64,D=512
// Projections + attention on legacy mma.sync bf16 hi/lo split tensor cores.
// GEMM: CTA 128x128, 4 warps (64x64), XOR-swizzled rows, cp.async, 2 CTAs/SM.
// Attention: 128-thread CTAs, Q frags direct from gmem, 128B swizzled KV rows,
// 3 CTAs/SM.

#define M_TOK 32768
#define N3D 1536
#define KD 512

__device__ float g_qkv[(size_t)M_TOK * N3D];
__device__ float g_attn[(size_t)M_TOK * 512];
__device__ float g_out1[(size_t)M_TOK * 512];
__device__ __nv_bfloat16 g_ahi[(size_t)M_TOK * KD];
__device__ __nv_bfloat16 g_alo[(size_t)M_TOK * KD];
__device__ __nv_bfloat16 g_whi[(size_t)N3D * KD];
__device__ __nv_bfloat16 g_wlo[(size_t)N3D * KD];

// ---------------------------------------------------------------------------
// helpers
// ---------------------------------------------------------------------------
__device__ __forceinline__ uint32_t smem_u32(const void* p) {
    uint32_t a;
    asm("{ .reg .u64 t; cvta.to.shared.u64 t, %1; cvt.u32.u64 %0, t; }" : "=r"(a) : "l"(p));
    return a;
}
__device__ __forceinline__ void ldsm4(uint32_t* r, uint32_t a) {
    asm volatile("ldmatrix.sync.aligned.m8n8.x4.shared.b16 {%0,%1,%2,%3}, [%4];"
        : "=r"(r[0]), "=r"(r[1]), "=r"(r[2]), "=r"(r[3]) : "r"(a));
}
__device__ __forceinline__ void ldsm2(uint32_t* r, uint32_t a) {
    asm volatile("ldmatrix.sync.aligned.m8n8.x2.shared.b16 {%0,%1}, [%2];"
        : "=r"(r[0]), "=r"(r[1]) : "r"(a));
}
__device__ __forceinline__ void ldsm2t(uint32_t* r, uint32_t a) {
    asm volatile("ldmatrix.sync.aligned.m8n8.x2.trans.shared.b16 {%0,%1}, [%2];"
        : "=r"(r[0]), "=r"(r[1]) : "r"(a));
}
__device__ __forceinline__ void mma_bf16(float* c, const uint32_t* a, const uint32_t* b) {
    asm volatile("mma.sync.aligned.m16n8k16.row.col.f32.bf16.bf16.f32 "
        "{%0,%1,%2,%3}, {%4,%5,%6,%7}, {%8,%9}, {%0,%1,%2,%3};"
        : "+f"(c[0]), "+f"(c[1]), "+f"(c[2]), "+f"(c[3])
        : "r"(a[0]), "r"(a[1]), "r"(a[2]), "r"(a[3]), "r"(b[0]), "r"(b[1]));
}
__device__ __forceinline__ uint32_t packbf(float lo, float hi) {
    uint32_t r;
    asm("cvt.rn.bf16x2.f32 %0, %1, %2;" : "=r"(r) : "f"(hi), "f"(lo));
    return r;
}
__device__ __forceinline__ float2 bfhi2f(uint32_t w) {
    float2 r;
    r.x = __uint_as_float(w << 16);
    r.y = __uint_as_float(w & 0xffff0000u);
    return r;
}
__device__ __forceinline__ void cpasync16(uint32_t dst, const void* src) {
    asm volatile("cp.async.cg.shared.global [%0], [%1], 16;" :: "r"(dst), "l"(src));
}
#define CP_COMMIT() asm volatile("cp.async.commit_group;" ::: "memory")
#define CP_WAIT1()  asm volatile("cp.async.wait_group 1;" ::: "memory")

// ---------------------------------------------------------------------------
// hi/lo bf16 split: hi = bf16(a), lo = bf16(a - float(hi))
// ---------------------------------------------------------------------------
__global__ void split_bf16(const float* __restrict__ in, __nv_bfloat16* __restrict__ hi,
                           __nv_bfloat16* __restrict__ lo, int n4) {
    int i = blockIdx.x * 256 + threadIdx.x;
    if (i >= n4) return;
    float4 v = ((const float4*)in)[i];
    uint32_t h0 = packbf(v.x, v.y), h1 = packbf(v.z, v.w);
    float2 f0 = bfhi2f(h0), f1 = bfhi2f(h1);
    ((uint32_t*)hi)[2*i]   = h0;
    ((uint32_t*)hi)[2*i+1] = h1;
    ((uint32_t*)lo)[2*i]   = packbf(v.x - f0.x, v.y - f0.y);
    ((uint32_t*)lo)[2*i+1] = packbf(v.z - f1.x, v.w - f1.y);
}

// ---------------------------------------------------------------------------
// GEMM via mma.sync (unchanged from R7): CTA 128x128, 4 warps (64x64),
// XOR-swizzled 64B rows, 3-stage cp.async, 2 CTAs/SM.
// ---------------------------------------------------------------------------
#define STG2   32768
#define RG_AHI 0
#define RG_ALO 8192
#define RG_WHI 16384
#define RG_WLO 24576
#define GEMM_SMEM (3 * STG2)

__global__ __launch_bounds__(128, 2)
void gemm_mma(const __nv_bfloat16* __restrict__ ahi, const __nv_bfloat16* __restrict__ alo,
              const __nv_bfloat16* __restrict__ whi, const __nv_bfloat16* __restrict__ wlo,
              const float* __restrict__ bias, float* __restrict__ C) {
    extern __shared__ char smg[];
    const uint32_t sb = smem_u32(smg);
    const int tid = threadIdx.x;
    const int lane = tid & 31, warp = tid >> 5;
    const int wm = (warp >> 1) * 64;
    const int wn = (warp & 1) * 64;
    const int m0 = blockIdx.y * 128;
    const int n0 = blockIdx.x * 128;

    const __nv_bfloat16* bases[4];
    bases[0] = ahi + (size_t)m0 * KD;
    bases[1] = alo + (size_t)m0 * KD;
    bases[2] = whi + (size_t)n0 * KD;
    bases[3] = wlo + (size_t)n0 * KD;
    const int lrow = tid >> 2;
    const int lv = tid & 3;
    const uint32_t dbase = (uint32_t)(lrow * 64 + ((lv ^ ((lrow >> 1) & 3)) << 4));
    const size_t goff = (size_t)lrow * KD + lv * 8;

    #define GEMM_ISSUE(kc) do { \
        uint32_t _s = sb + ((kc) % 3) * STG2 + dbase; \
        _Pragma("unroll") \
        for (int rg = 0; rg < 4; rg++) { \
            const __nv_bfloat16* _b = bases[rg] + goff + (kc) * 32; \
            _Pragma("unroll") \
            for (int j = 0; j < 4; j++) \
                cpasync16(_s + rg * 8192 + j * 2048, _b + (size_t)j * 32 * KD); \
        } \
        CP_COMMIT(); \
    } while (0)

    GEMM_ISSUE(0);
    GEMM_ISSUE(1);

    float acc[4][8][4];
    #pragma unroll
    for (int mt = 0; mt < 4; mt++)
        #pragma unroll
        for (int nt = 0; nt < 8; nt++)
            #pragma unroll
            for (int e = 0; e < 4; e++) acc[mt][nt][e] = 0.f;

    const uint32_t fr = lane & 15;
    const uint32_t fahi = lane >> 4;
    const uint32_t fbr = (lane & 7) + ((lane >> 4) << 3);
    const uint32_t fbhi = (lane >> 3) & 1;

    for (int kc = 0; kc < KD / 32; kc++) {
        CP_WAIT1();
        __syncthreads();
        if (kc + 2 < KD / 32) GEMM_ISSUE(kc + 2);

        const uint32_t st = sb + (kc % 3) * STG2;
        #pragma unroll
        for (int ks = 0; ks < 2; ks++) {
            uint32_t ah[4][4], bh[4][4];
            #pragma unroll
            for (int mt = 0; mt < 4; mt++) {
                uint32_t R = wm + mt * 16 + fr;
                uint32_t c16 = (ks * 2 + fahi) ^ ((R >> 1) & 3);
                ldsm4(ah[mt], st + RG_AHI + R * 64 + c16 * 16);
            }
            #pragma unroll
            for (int np = 0; np < 4; np++) {
                uint32_t R = wn + np * 16 + fbr;
                uint32_t c16 = (ks * 2 + fbhi) ^ ((R >> 1) & 3);
                ldsm4(bh[np], st + RG_WHI + R * 64 + c16 * 16);
            }
            #pragma unroll
            for (int mt = 0; mt < 4; mt++)
                #pragma unroll
                for (int nt = 0; nt < 8; nt++)
                    mma_bf16(acc[mt][nt], ah[mt], &bh[nt >> 1][(nt & 1) * 2]);

            uint32_t bl[4][4];
            #pragma unroll
            for (int np = 0; np < 4; np++) {
                uint32_t R = wn + np * 16 + fbr;
                uint32_t c16 = (ks * 2 + fbhi) ^ ((R >> 1) & 3);
                ldsm4(bl[np], st + RG_WLO + R * 64 + c16 * 16);
            }
            #pragma unroll
            for (int mt = 0; mt < 4; mt++)
                #pragma unroll
                for (int nt = 0; nt < 8; nt++)
                    mma_bf16(acc[mt][nt], ah[mt], &bl[nt >> 1][(nt & 1) * 2]);

            uint32_t al[4][4];
            #pragma unroll
            for (int mt = 0; mt < 4; mt++) {
                uint32_t R = wm + mt * 16 + fr;
                uint32_t c16 = (ks * 2 + fahi) ^ ((R >> 1) & 3);
                ldsm4(al[mt], st + RG_ALO + R * 64 + c16 * 16);
            }
            #pragma unroll
            for (int mt = 0; mt < 4; mt++)
                #pragma unroll
                for (int nt = 0; nt < 8; nt++)
                    mma_bf16(acc[mt][nt], al[mt], &bh[nt >> 1][(nt & 1) * 2]);
        }
    }

    #pragma unroll
    for (int mt = 0; mt < 4; mt++) {
        int row0 = m0 + wm + mt * 16 + (lane >> 2);
        #pragma unroll
        for (int nt = 0; nt < 8; nt++) {
            int col = n0 + wn + nt * 8 + (lane & 3) * 2;
            float2 bv = *(const float2*)&bias[col];
            float2 o0, o1;
            o0.x = acc[mt][nt][0] + bv.x; o0.y = acc[mt][nt][1] + bv.y;
            o1.x = acc[mt][nt][2] + bv.x; o1.y = acc[mt][nt][3] + bv.y;
            *(float2*)&C[(size_t)row0 * N3D + col] = o0;
            *(float2*)&C[(size_t)(row0 + 8) * N3D + col] = o1;
        }
    }
}

// ---------------------------------------------------------------------------
// Flash attention via mma.sync, bf16 hi/lo split.
// 128-thread CTAs, 4 warps x 16 q-rows = 64 rows per CTA.
// ISROW: CTA=(b,s,h,rowblock of 64), keys=256 staged in 2 chunks of 128.
// !ISROW: CTA=(b,l,h), keys=64, 1 chunk.
// K/V smem: exact 128B rows, XOR swizzle c16^=(row&7). Q frags direct LDG.
// ---------------------------------------------------------------------------
template<bool ISROW>
__global__ __launch_bounds__(128, 3)
void attn_mma(const float* __restrict__ qkv, float* __restrict__ out) {
    constexpr int CHUNK = ISROW ? 128 : 64;     // keys per staged chunk
    constexpr int NCHUNK = ISROW ? 2 : 1;
    constexpr int TPC = CHUNK / 64;             // 64-key tiles per chunk
    constexpr uint32_t CB = CHUNK * 128;        // bytes per matrix
    extern __shared__ char sm[];
    const uint32_t sb = smem_u32(sm);
    const int tid = threadIdx.x, lane = tid & 31, warp = tid >> 5;
    const int bid = blockIdx.x;

    int h, b, rb = 0, lcoord = 0;
    long tok0 = 0;
    if (ISROW) {
        rb = bid & 3; h = (bid >> 2) & 7;
        int s = (bid >> 5) & 63; b = bid >> 11;
        tok0 = (long)(b * 64 + s) * 256;
    } else {
        h = bid & 7; lcoord = (bid >> 3) & 255; b = bid >> 11;
    }

    // ---- Q fragments direct from gmem (warp owns q-rows warp*16..+15) ----
    const int qr = warp * 16 + (lane >> 2);
    const long tq0 = ISROW ? (tok0 + rb * 64 + qr)
                           : ((long)(b * 64 + qr) * 256 + lcoord);
    const long tq1 = ISROW ? (tq0 + 8) : (tq0 + 8 * 256);
    const float* q0p = qkv + tq0 * 1536 + h * 64 + (lane & 3) * 2;
    const float* q1p = qkv + tq1 * 1536 + h * 64 + (lane & 3) * 2;
    uint32_t qh[4][4], ql[4][4];
    #pragma unroll
    for (int kt = 0; kt < 4; kt++) {
        float2 qa = *(const float2*)(q0p + kt * 16);
        float2 qb = *(const float2*)(q1p + kt * 16);
        float2 qc = *(const float2*)(q0p + kt * 16 + 8);
        float2 qd = *(const float2*)(q1p + kt * 16 + 8);
        uint32_t wa = packbf(qa.x, qa.y), wb = packbf(qb.x, qb.y);
        uint32_t wc = packbf(qc.x, qc.y), wd = packbf(qd.x, qd.y);
        qh[kt][0] = wa; qh[kt][1] = wb; qh[kt][2] = wc; qh[kt][3] = wd;
        float2 fa = bfhi2f(wa), fb = bfhi2f(wb), fc = bfhi2f(wc), fd = bfhi2f(wd);
        ql[kt][0] = packbf(qa.x - fa.x, qa.y - fa.y);
        ql[kt][1] = packbf(qb.x - fb.x, qb.y - fb.y);
        ql[kt][2] = packbf(qc.x - fc.x, qc.y - fc.y);
        ql[kt][3] = packbf(qd.x - fd.x, qd.y - fd.y);
    }

    float O[8][4];
    #pragma unroll
    for (int nv = 0; nv < 8; nv++)
        #pragma unroll
        for (int e = 0; e < 4; e++) O[nv][e] = 0.f;
    float m0 = -1e30f, m1 = -1e30f, l0 = 0.f, l1 = 0.f;

    const uint32_t swl = (uint32_t)(lane & 7);       // row%8 == lane&7 everywhere
    const uint32_t khalf = (uint32_t)((lane >> 3) & 1);

    for (int cnk = 0; cnk < NCHUNK; cnk++) {
        if (cnk) __syncthreads();
        // ---- stage K/V chunk: fp32 gmem -> bf16 hi/lo swizzled smem ----
        for (int idx = tid; idx < CHUNK * 16; idx += 128) {
            int j = idx >> 4, c4 = idx & 15;
            long kt_ = ISROW ? (tok0 + cnk * CHUNK + j)
                             : ((long)(b * 64 + j) * 256 + lcoord);
            const float* p = qkv + kt_ * 1536 + h * 64 + c4 * 4;
            float4 kf = *(const float4*)(p + 512);
            float4 vf = *(const float4*)(p + 1024);
            uint32_t kh0 = packbf(kf.x, kf.y), kh1 = packbf(kf.z, kf.w);
            uint32_t vh0 = packbf(vf.x, vf.y), vh1 = packbf(vf.z, vf.w);
            float2 e0 = bfhi2f(kh0), e1 = bfhi2f(kh1);
            float2 g0 = bfhi2f(vh0), g1 = bfhi2f(vh1);
            uint32_t off = (uint32_t)(j * 128 + ((((c4 >> 1) ^ (j & 7)) << 4) | ((c4 & 1) << 3)));
            *(uint2*)(sm + off)          = make_uint2(kh0, kh1);
            *(uint2*)(sm + CB + off)     = make_uint2(packbf(kf.x - e0.x, kf.y - e0.y),
                                                      packbf(kf.z - e1.x, kf.w - e1.y));
            *(uint2*)(sm + 2 * CB + off) = make_uint2(vh0, vh1);
            *(uint2*)(sm + 3 * CB + off) = make_uint2(packbf(vf.x - g0.x, vf.y - g0.y),
                                                      packbf(vf.z - g1.x, vf.w - g1.y));
        }
        __syncthreads();

        #pragma unroll
        for (int t = 0; t < TPC; t++) {
            const int j0 = t * 64;
            float S[8][4];
            #pragma unroll
            for (int nt = 0; nt < 8; nt++)
                #pragma unroll
                for (int e = 0; e < 4; e++) S[nt][e] = 0.f;

            // ---- QK^T ----
            #pragma unroll
            for (int c = 0; c < 4; c++) {
                const uint32_t csw = (((uint32_t)(2 * c) + khalf) ^ swl) << 4;
                #pragma unroll
                for (int nt = 0; nt < 8; nt++) {
                    uint32_t ka = sb + (uint32_t)(j0 + nt * 8) * 128 + swl * 128 + csw;
                    uint32_t kh2[2], kl2[2];
                    ldsm2(kh2, ka);
                    ldsm2(kl2, ka + CB);
                    mma_bf16(S[nt], qh[c], kh2);
                    mma_bf16(S[nt], qh[c], kl2);
                    mma_bf16(S[nt], ql[c], kh2);
                }
            }

            // ---- online softmax ----
            float mx0 = S[0][0], mx1 = S[0][2];
            #pragma unroll
            for (int nt = 0; nt < 8; nt++) {
                mx0 = fmaxf(mx0, fmaxf(S[nt][0], S[nt][1]));
                mx1 = fmaxf(mx1, fmaxf(S[nt][2], S[nt][3]));
            }
            mx0 = fmaxf(mx0, __shfl_xor_sync(0xffffffffu, mx0, 1));
            mx0 = fmaxf(mx0, __shfl_xor_sync(0xffffffffu, mx0, 2));
            mx1 = fmaxf(mx1, __shfl_xor_sync(0xffffffffu, mx1, 1));
            mx1 = fmaxf(mx1, __shfl_xor_sync(0xffffffffu, mx1, 2));
            float mn0 = fmaxf(m0, mx0), mn1 = fmaxf(m1, mx1);
            float sc0 = __expf(m0 - mn0), sc1 = __expf(m1 - mn1);
            m0 = mn0; m1 = mn1;

            float sum0 = 0.f, sum1 = 0.f;
            #pragma unroll
            for (int nt = 0; nt < 8; nt++) {
                S[nt][0] = __expf(S[nt][0] - m0);
                S[nt][1] = __expf(S[nt][1] - m0);
                S[nt][2] = __expf(S[nt][2] - m1);
                S[nt][3] = __expf(S[nt][3] - m1);
                sum0 += S[nt][0] + S[nt][1];
                sum1 += S[nt][2] + S[nt][3];
            }
            sum0 += __shfl_xor_sync(0xffffffffu, sum0, 1);
            sum0 += __shfl_xor_sync(0xffffffffu, sum0, 2);
            sum1 += __shfl_xor_sync(0xffffffffu, sum1, 1);
            sum1 += __shfl_xor_sync(0xffffffffu, sum1, 2);
            l0 = l0 * sc0 + sum0;
            l1 = l1 * sc1 + sum1;
            #pragma unroll
            for (int nv = 0; nv < 8; nv++) {
                O[nv][0] *= sc0; O[nv][1] *= sc0;
                O[nv][2] *= sc1; O[nv][3] *= sc1;
            }

            // ---- P·V ----
            #pragma unroll
            for (int kp = 0; kp < 4; kp++) {
                uint32_t aph[4], apl[4];
                #pragma unroll
                for (int half = 0; half < 2; half++) {
                    const float* Sv = S[2 * kp + half];
                    uint32_t w0 = packbf(Sv[0], Sv[1]);
                    uint32_t w1 = packbf(Sv[2], Sv[3]);
                    float2 h0 = bfhi2f(w0), h1 = bfhi2f(w1);
                    aph[2 * half]     = w0;
                    aph[2 * half + 1] = w1;
                    apl[2 * half]     = packbf(Sv[0] - h0.x, Sv[1] - h0.y);
                    apl[2 * half + 1] = packbf(Sv[2] - h1.x, Sv[3] - h1.y);
                }
                const uint32_t vr = (uint32_t)(j0 + kp * 16) + khalf * 8 + swl;
                #pragma unroll
                for (int nv = 0; nv < 8; nv++) {
                    uint32_t va = sb + 2 * CB + vr * 128 + ((((uint32_t)nv ^ swl)) << 4);
                    uint32_t vh2[2], vl2[2];
                    ldsm2t(vh2, va);
                    ldsm2t(vl2, va + CB);
                    mma_bf16(O[nv], aph, vh2);
                    mma_bf16(O[nv], aph, vl2);
                    mma_bf16(O[nv], apl, vh2);
                }
            }
        }
    }

    // ---- write out ----
    float inv0 = 1.f / l0, inv1 = 1.f / l1;
    #pragma unroll
    for (int nv = 0; nv < 8; nv++) {
        int col = h * 64 + nv * 8 + (lane & 3) * 2;
        float2 o0, o1;
        o0.x = O[nv][0] * inv0; o0.y = O[nv][1] * inv0;
        o1.x = O[nv][2] * inv1; o1.y = O[nv][3] * inv1;
        *(float2*)&out[tq0 * 512 + col] = o0;
        *(float2*)&out[tq1 * 512 + col] = o1;
    }
}

// ---------------------------------------------------------------------------
// out = LayerNorm(a + b) * g + beta; optionally also emit bf16 hi/lo split.
// ---------------------------------------------------------------------------
template<bool SPLIT>
__global__ void add_ln(const float* __restrict__ a, const float* __restrict__ b,
                       const float* __restrict__ g, const float* __restrict__ be,
                       float* __restrict__ out,
                       __nv_bfloat16* __restrict__ hi, __nv_bfloat16* __restrict__ lo) {
    int row = blockIdx.x * 8 + (threadIdx.x >> 5);
    int lane = threadIdx.x & 31;
    const float* pa = a + (size_t)row * 512;
    const float* pb = b + (size_t)row * 512;
    float v[16];
    float sum = 0.f;
    #pragma unroll
    for (int i = 0; i < 4; i++) {
        int c = lane * 4 + i * 128;
        float4 x = *(const float4*)&pa[c];
        float4 y = *(const float4*)&pb[c];
        v[i*4+0] = x.x + y.x; v[i*4+1] = x.y + y.y;
        v[i*4+2] = x.z + y.z; v[i*4+3] = x.w + y.w;
        sum += v[i*4+0] + v[i*4+1] + v[i*4+2] + v[i*4+3];
    }
    #pragma unroll
    for (int o = 16; o > 0; o >>= 1) sum += __shfl_xor_sync(0xffffffffu, sum, o);
    float mu = sum * (1.f / 512.f);
    float var = 0.f;
    #pragma unroll
    for (int i = 0; i < 16; i++) { float d = v[i] - mu; var += d * d; }
    #pragma unroll
    for (int o = 16; o > 0; o >>= 1) var += __shfl_xor_sync(0xffffffffu, var, o);
    float rstd = rsqrtf(var * (1.f / 512.f) + 1e-5f);
    float* po = out + (size_t)row * 512;
    #pragma unroll
    for (int i = 0; i < 4; i++) {
        int c = lane * 4 + i * 128;
        float4 gg = *(const float4*)&g[c];
        float4 bb = *(const float4*)&be[c];
        float4 o4;
        o4.x = (v[i*4+0] - mu) * rstd * gg.x + bb.x;
        o4.y = (v[i*4+1] - mu) * rstd * gg.y + bb.y;
        o4.z = (v[i*4+2] - mu) * rstd * gg.z + bb.z;
        o4.w = (v[i*4+3] - mu) * rstd * gg.w + bb.w;
        *(float4*)&po[c] = o4;
        if (SPLIT) {
            uint32_t h0 = packbf(o4.x, o4.y), h1 = packbf(o4.z, o4.w);
            float2 f0 = bfhi2f(h0), f1 = bfhi2f(h1);
            size_t w = (size_t)row * 256 + c / 2;
            ((uint32_t*)hi)[w]     = h0;
            ((uint32_t*)hi)[w + 1] = h1;
            ((uint32_t*)lo)[w]     = packbf(o4.x - f0.x, o4.y - f0.y);
            ((uint32_t*)lo)[w + 1] = packbf(o4.z - f1.x, o4.w - f1.y);
        }
    }
}

// ---------------------------------------------------------------------------

extern "C" void kernel_launch(void* const* d_in, const int* in_sizes, int n_in,
                              void* d_out, int out_size) {
    const float* x     = (const float*)d_in[0];
    const float* w_row = (const float*)d_in[1];
    const float* b_row = (const float*)d_in[2];
    const float* w_col = (const float*)d_in[3];
    const float* b_col = (const float*)d_in[4];
    const float* g1    = (const float*)d_in[5];
    const float* be1   = (const float*)d_in[6];
    const float* g2    = (const float*)d_in[7];
    const float* be2   = (const float*)d_in[8];
    float* out = (float*)d_out;

    float *qkv, *attn, *out1;
    __nv_bfloat16 *ahi, *alo, *whi, *wlo;
    cudaGetSymbolAddress((void**)&qkv,  g_qkv);
    cudaGetSymbolAddress((void**)&attn, g_attn);
    cudaGetSymbolAddress((void**)&out1, g_out1);
    cudaGetSymbolAddress((void**)&ahi,  g_ahi);
    cudaGetSymbolAddress((void**)&alo,  g_alo);
    cudaGetSymbolAddress((void**)&whi,  g_whi);
    cudaGetSymbolAddress((void**)&wlo,  g_wlo);

    const int smem_row = 4 * 128 * 128;   // 65536
    const int smem_col = 4 * 64 * 128;    // 32768
    cudaFuncSetAttribute(attn_mma<true>,
                         cudaFuncAttributeMaxDynamicSharedMemorySize, smem_row);
    cudaFuncSetAttribute(attn_mma<false>,
                         cudaFuncAttributeMaxDynamicSharedMemorySize, smem_col);
    cudaFuncSetAttribute(gemm_mma,
                         cudaFuncAttributeMaxDynamicSharedMemorySize, GEMM_SMEM);

    const int n4x = M_TOK * KD / 4;
    const int n4w = N3D * KD / 4;
    dim3 ggrid(N3D / 128, M_TOK / 128);   // (12, 256)

    split_bf16<<<(n4x + 255) / 256, 256>>>(x, ahi, alo, n4x);
    split_bf16<<<(n4w + 255) / 256, 256>>>(w_row, whi, wlo, n4w);
    gemm_mma<<<ggrid, 128, GEMM_SMEM>>>(ahi, alo, whi, wlo, b_row, qkv);
    attn_mma<true><<<4096, 128, smem_row>>>(qkv, attn);
    add_ln<true><<<M_TOK / 8, 256>>>(x, attn, g1, be1, out1, ahi, alo);

    split_bf16<<<(n4w + 255) / 256, 256>>>(w_col, whi, wlo, n4w);
    gemm_mma<<<ggrid, 128, GEMM_SMEM>>>(ahi, alo, whi, wlo, b_col, qkv);
    attn_mma<false><<<4096, 128, smem_col>>>(qkv, attn);
    add_ln<false><<<M_TOK / 8, 256>>>(out1, attn, g2, be2, out, nullptr, nullptr);
}